// round 1
// baseline (speedup 1.0000x reference)
#include <cuda_runtime.h>
#include <math.h>

// Problem constants
#define B_  16
#define CI  512
#define HW  1024
#define CA  512
#define KL  256
#define NH  8
#define HD  64

// Scratch (allocation-free: __device__ globals)
__device__ float g_q[B_*HW*CA];     // scaled Q  [b, s, c]
__device__ float g_k[B_*KL*CA];     // K         [b, t, c]
__device__ float g_v[B_*KL*CA];     // V         [b, t, c]
__device__ float g_attn[B_*HW*CA];  // attention output merged [b, s, c]
__device__ float g_y[B_*HW*CI];     // pre-LN residual sum     [b, s, c]

// ---------------------------------------------------------------------------
// Q projection: q[b,s,c] = (sum_k img[b,k,s] * Wq[k,c] + bq[c]) * 0.125
// A is read "transposed" (k-major rows, contiguous in s) -> naturally coalesced.
// 64x64 tile, BK=16, 256 threads, 4x4 register tile.
// ---------------------------------------------------------------------------
__global__ void gemm_q_kernel(const float* __restrict__ img,
                              const float* __restrict__ Wq,
                              const float* __restrict__ bq)
{
    __shared__ float As[16][65];   // [kk][s]
    __shared__ float Bs[16][65];   // [kk][c]
    const int s0 = blockIdx.x * 64;
    const int c0 = blockIdx.y * 64;
    const int b  = blockIdx.z;
    const int tid = threadIdx.x;
    const int tx = tid & 15, ty = tid >> 4;
    const int lr = tid >> 6, lc = tid & 63;

    const float* A = img + (size_t)b * CI * HW;
    float acc[4][4];
#pragma unroll
    for (int i = 0; i < 4; i++)
#pragma unroll
        for (int j = 0; j < 4; j++) acc[i][j] = 0.f;

    for (int k0 = 0; k0 < CI; k0 += 16) {
#pragma unroll
        for (int i = 0; i < 4; i++) {
            As[lr + 4*i][lc] = A[(size_t)(k0 + lr + 4*i) * HW + s0 + lc];
            Bs[lr + 4*i][lc] = Wq[(size_t)(k0 + lr + 4*i) * CA + c0 + lc];
        }
        __syncthreads();
#pragma unroll
        for (int kk = 0; kk < 16; kk++) {
            float a[4], bb[4];
#pragma unroll
            for (int i = 0; i < 4; i++) a[i]  = As[kk][ty*4 + i];
#pragma unroll
            for (int j = 0; j < 4; j++) bb[j] = Bs[kk][tx*4 + j];
#pragma unroll
            for (int i = 0; i < 4; i++)
#pragma unroll
                for (int j = 0; j < 4; j++)
                    acc[i][j] = fmaf(a[i], bb[j], acc[i][j]);
        }
        __syncthreads();
    }
#pragma unroll
    for (int j = 0; j < 4; j++) {
        const float bias = bq[c0 + tx*4 + j];
#pragma unroll
        for (int i = 0; i < 4; i++) {
            const int s = s0 + ty*4 + i;
            g_q[((size_t)b*HW + s)*CA + c0 + tx*4 + j] = (acc[i][j] + bias) * 0.125f;
        }
    }
}

// ---------------------------------------------------------------------------
// K and V projections fused: share the A (audio) tile, two B tiles.
// A is row-major [t, k]; loaded with smem transpose.
// ---------------------------------------------------------------------------
__global__ void gemm_kv_kernel(const float* __restrict__ aud,
                               const float* __restrict__ Wk, const float* __restrict__ bk,
                               const float* __restrict__ Wv, const float* __restrict__ bv)
{
    __shared__ float As[16][65];   // [kk][t]
    __shared__ float Bk[16][65];
    __shared__ float Bv[16][65];
    const int t0 = blockIdx.x * 64;
    const int c0 = blockIdx.y * 64;
    const int b  = blockIdx.z;
    const int tid = threadIdx.x;
    const int tx = tid & 15, ty = tid >> 4;
    const int lkk = tid & 15, lmm = tid >> 4;
    const int lr = tid >> 6, lc = tid & 63;

    const float* A = aud + (size_t)b * KL * CA;
    float ak[4][4], av[4][4];
#pragma unroll
    for (int i = 0; i < 4; i++)
#pragma unroll
        for (int j = 0; j < 4; j++) { ak[i][j] = 0.f; av[i][j] = 0.f; }

    for (int k0 = 0; k0 < CA; k0 += 16) {
#pragma unroll
        for (int i = 0; i < 4; i++) {
            As[lkk][lmm + 16*i] = A[(size_t)(t0 + lmm + 16*i) * CA + k0 + lkk];
            Bk[lr + 4*i][lc] = Wk[(size_t)(k0 + lr + 4*i) * CA + c0 + lc];
            Bv[lr + 4*i][lc] = Wv[(size_t)(k0 + lr + 4*i) * CA + c0 + lc];
        }
        __syncthreads();
#pragma unroll
        for (int kk = 0; kk < 16; kk++) {
            float a[4], bkr[4], bvr[4];
#pragma unroll
            for (int i = 0; i < 4; i++) a[i]   = As[kk][ty*4 + i];
#pragma unroll
            for (int j = 0; j < 4; j++) { bkr[j] = Bk[kk][tx*4 + j]; bvr[j] = Bv[kk][tx*4 + j]; }
#pragma unroll
            for (int i = 0; i < 4; i++)
#pragma unroll
                for (int j = 0; j < 4; j++) {
                    ak[i][j] = fmaf(a[i], bkr[j], ak[i][j]);
                    av[i][j] = fmaf(a[i], bvr[j], av[i][j]);
                }
        }
        __syncthreads();
    }
#pragma unroll
    for (int j = 0; j < 4; j++) {
        const int c = c0 + tx*4 + j;
        const float bkb = bk[c], bvb = bv[c];
#pragma unroll
        for (int i = 0; i < 4; i++) {
            const size_t idx = ((size_t)b*KL + t0 + ty*4 + i)*CA + c;
            g_k[idx] = ak[i][j] + bkb;
            g_v[idx] = av[i][j] + bvb;
        }
    }
}

// ---------------------------------------------------------------------------
// Attention: one CTA per (b, h, 128-query tile). K_LEN=256 keys.
// Full 128x256 score matrix in smem; K/V streamed in 64-row chunks.
// ---------------------------------------------------------------------------
#define ATTN_SMEM_FLOATS (128*257 + 128*65 + 64*65)

__global__ void attn_kernel()
{
    extern __shared__ float sm[];
    float* S  = sm;                 // [128][257]
    float* Qs = sm + 128*257;       // [128][65]
    float* Ks = Qs + 128*65;        // [64][65] (reused for V)

    const int s0 = blockIdx.x * 128;
    const int h  = blockIdx.y;
    const int b  = blockIdx.z;
    const int t  = threadIdx.x;     // 256 threads
    const int tx = t & 63, ty = t >> 6;

    const float* qb = g_q + ((size_t)b*HW + s0)*CA + h*HD;
    const float* kb = g_k + (size_t)b*KL*CA + h*HD;
    const float* vb = g_v + (size_t)b*KL*CA + h*HD;

    for (int idx = t; idx < 128*64; idx += 256) {
        const int r = idx >> 6, d = idx & 63;
        Qs[r*65 + d] = qb[(size_t)r*CA + d];
    }

    // ---- scores: S = Q K^T (Q pre-scaled by 1/sqrt(64)) ----
    for (int kc = 0; kc < 4; kc++) {
        __syncthreads();
        for (int idx = t; idx < 64*64; idx += 256) {
            const int r = idx >> 6, d = idx & 63;
            Ks[r*65 + d] = kb[(size_t)(kc*64 + r)*CA + d];
        }
        __syncthreads();
        for (int i = 0; i < 32; i++) {
            const int r = ty + 4*i;
            float acc = 0.f;
#pragma unroll
            for (int d = 0; d < 64; d++)
                acc = fmaf(Qs[r*65 + d], Ks[tx*65 + d], acc);
            S[r*257 + kc*64 + tx] = acc;
        }
    }
    __syncthreads();

    // ---- softmax over 256 keys, one warp per row ----
    {
        const int wid = t >> 5, lid = t & 31;
        for (int ri = 0; ri < 16; ri++) {
            const int r = wid + 8*ri;
            float vals[8];
            float m = -1e30f;
#pragma unroll
            for (int ii = 0; ii < 8; ii++) {
                vals[ii] = S[r*257 + lid + 32*ii];
                m = fmaxf(m, vals[ii]);
            }
#pragma unroll
            for (int off = 16; off; off >>= 1) m = fmaxf(m, __shfl_xor_sync(0xffffffffu, m, off));
            float sum = 0.f;
#pragma unroll
            for (int ii = 0; ii < 8; ii++) { vals[ii] = __expf(vals[ii] - m); sum += vals[ii]; }
#pragma unroll
            for (int off = 16; off; off >>= 1) sum += __shfl_xor_sync(0xffffffffu, sum, off);
            const float inv = 1.f / sum;
#pragma unroll
            for (int ii = 0; ii < 8; ii++) S[r*257 + lid + 32*ii] = vals[ii] * inv;
        }
    }

    // ---- O = P V ----
    float oacc[32];
#pragma unroll
    for (int i = 0; i < 32; i++) oacc[i] = 0.f;

    for (int kc = 0; kc < 4; kc++) {
        __syncthreads();
        for (int idx = t; idx < 64*64; idx += 256) {
            const int r = idx >> 6, d = idx & 63;
            Ks[r*65 + d] = vb[(size_t)(kc*64 + r)*CA + d];
        }
        __syncthreads();
        for (int i = 0; i < 32; i++) {
            const int r = ty + 4*i;
            float a = oacc[i];
#pragma unroll
            for (int j = 0; j < 64; j++)
                a = fmaf(S[r*257 + kc*64 + j], Ks[j*65 + tx], a);
            oacc[i] = a;
        }
    }

    float* ob = g_attn + ((size_t)b*HW + s0)*CA + h*HD;
    for (int i = 0; i < 32; i++) {
        const int r = ty + 4*i;
        ob[(size_t)r*CA + tx] = oacc[i];
    }
}

// ---------------------------------------------------------------------------
// O projection + bias + residual: y[b,s,c] = attn[b,s,:] @ Wo + bo + img[b,c,s]
// ---------------------------------------------------------------------------
__global__ void gemm_o_kernel(const float* __restrict__ img,
                              const float* __restrict__ Wo,
                              const float* __restrict__ bo)
{
    __shared__ float As[16][65];
    __shared__ float Bs[16][65];
    const int s0 = blockIdx.x * 64;
    const int c0 = blockIdx.y * 64;
    const int b  = blockIdx.z;
    const int tid = threadIdx.x;
    const int tx = tid & 15, ty = tid >> 4;
    const int lkk = tid & 15, lmm = tid >> 4;
    const int lr = tid >> 6, lc = tid & 63;

    const float* A = g_attn + (size_t)b * HW * CA;
    float acc[4][4];
#pragma unroll
    for (int i = 0; i < 4; i++)
#pragma unroll
        for (int j = 0; j < 4; j++) acc[i][j] = 0.f;

    for (int k0 = 0; k0 < CA; k0 += 16) {
#pragma unroll
        for (int i = 0; i < 4; i++) {
            As[lkk][lmm + 16*i] = A[(size_t)(s0 + lmm + 16*i) * CA + k0 + lkk];
            Bs[lr + 4*i][lc] = Wo[(size_t)(k0 + lr + 4*i) * CI + c0 + lc];
        }
        __syncthreads();
#pragma unroll
        for (int kk = 0; kk < 16; kk++) {
            float a[4], bb[4];
#pragma unroll
            for (int i = 0; i < 4; i++) a[i]  = As[kk][ty*4 + i];
#pragma unroll
            for (int j = 0; j < 4; j++) bb[j] = Bs[kk][tx*4 + j];
#pragma unroll
            for (int i = 0; i < 4; i++)
#pragma unroll
                for (int j = 0; j < 4; j++)
                    acc[i][j] = fmaf(a[i], bb[j], acc[i][j]);
        }
        __syncthreads();
    }
#pragma unroll
    for (int j = 0; j < 4; j++) {
        const int c = c0 + tx*4 + j;
        const float bias = bo[c];
#pragma unroll
        for (int i = 0; i < 4; i++) {
            const int s = s0 + ty*4 + i;
            g_y[((size_t)b*HW + s)*CI + c] =
                acc[i][j] + bias + img[(size_t)b*CI*HW + (size_t)c*HW + s];
        }
    }
}

// ---------------------------------------------------------------------------
// LayerNorm over channels + transpose to [b, c, h*w]
// one CTA (256 threads) per (b, s) row of 512 channels
// ---------------------------------------------------------------------------
__global__ void ln_kernel(const float* __restrict__ gamma,
                          const float* __restrict__ beta,
                          float* __restrict__ out)
{
    const int row = blockIdx.x;          // b*1024 + s
    const int b = row >> 10, s = row & 1023;
    const int t = threadIdx.x;           // 256
    const float* yr = g_y + (size_t)row * CI;

    const float x0 = yr[t];
    const float x1 = yr[t + 256];
    float sum = x0 + x1;
    float sq  = x0*x0 + x1*x1;
#pragma unroll
    for (int off = 16; off; off >>= 1) {
        sum += __shfl_xor_sync(0xffffffffu, sum, off);
        sq  += __shfl_xor_sync(0xffffffffu, sq,  off);
    }
    __shared__ float sms[8], smq[8];
    __shared__ float s_mu, s_inv;
    const int wid = t >> 5, lid = t & 31;
    if (lid == 0) { sms[wid] = sum; smq[wid] = sq; }
    __syncthreads();
    if (t == 0) {
        float S = 0.f, Q = 0.f;
#pragma unroll
        for (int i = 0; i < 8; i++) { S += sms[i]; Q += smq[i]; }
        const float mu  = S * (1.f/512.f);
        const float var = Q * (1.f/512.f) - mu*mu;
        s_mu = mu;
        s_inv = rsqrtf(var + 1e-5f);
    }
    __syncthreads();
    const float mu = s_mu, inv = s_inv;
    out[((size_t)b*CI + t      )*HW + s] = (x0 - mu)*inv*gamma[t]       + beta[t];
    out[((size_t)b*CI + t + 256)*HW + s] = (x1 - mu)*inv*gamma[t + 256] + beta[t + 256];
}

// ---------------------------------------------------------------------------
extern "C" void kernel_launch(void* const* d_in, const int* in_sizes, int n_in,
                              void* d_out, int out_size)
{
    (void)in_sizes; (void)n_in; (void)out_size;
    const float* img   = (const float*)d_in[0];
    const float* aud   = (const float*)d_in[1];
    const float* Wq    = (const float*)d_in[2];
    const float* bq    = (const float*)d_in[3];
    const float* Wk    = (const float*)d_in[4];
    const float* bk    = (const float*)d_in[5];
    const float* Wv    = (const float*)d_in[6];
    const float* bv    = (const float*)d_in[7];
    const float* Wo    = (const float*)d_in[8];
    const float* bo    = (const float*)d_in[9];
    const float* gamma = (const float*)d_in[10];
    const float* beta  = (const float*)d_in[11];
    float* out = (float*)d_out;

    gemm_q_kernel<<<dim3(HW/64, CA/64, B_), 256>>>(img, Wq, bq);
    gemm_kv_kernel<<<dim3(KL/64, CA/64, B_), 256>>>(aud, Wk, bk, Wv, bv);

    const size_t attn_smem = (size_t)ATTN_SMEM_FLOATS * sizeof(float);
    cudaFuncSetAttribute(attn_kernel, cudaFuncAttributeMaxDynamicSharedMemorySize,
                         (int)attn_smem);
    attn_kernel<<<dim3(HW/128, NH, B_), 256, attn_smem>>>();

    gemm_o_kernel<<<dim3(HW/64, CI/64, B_), 256>>>(img, Wo, bo);
    ln_kernel<<<B_*HW, 256>>>(gamma, beta, out);
}

// round 2
// speedup vs baseline: 1.7920x; 1.7920x over previous
#include <cuda_runtime.h>
#include <math.h>

#define B_  16
#define CI  512
#define HW  1024
#define CA  512
#define KL  256
#define NH  8
#define HD  64

// Scratch (allocation-free: __device__ globals)
__device__ float g_q[B_*HW*CA];     // scaled Q  [b, s, c]
__device__ float g_k[B_*KL*CA];     // K         [b, t, c]
__device__ float g_v[B_*KL*CA];     // V         [b, t, c]
__device__ float g_attn[B_*HW*CA];  // attention output merged [b, s, c]
__device__ float g_y[B_*HW*CI];     // pre-LN residual sum     [b, s, c]

// ---------------------------------------------------------------------------
// Q projection: q[b,s,c] = (sum_k img[b,k,s]*Wq[k,c] + bq[c]) * 0.125
// A is k-major (contiguous in s) -> direct coalesced loads into As[kk][m].
// 128x128 tile, BK=16, 256 threads, 8x8 micro-tile, all-LDS.128 inner loop.
// ---------------------------------------------------------------------------
__global__ void __launch_bounds__(256) gemm_q_kernel(
    const float* __restrict__ img, const float* __restrict__ Wq,
    const float* __restrict__ bq)
{
    __shared__ float As[16][132];
    __shared__ float Bs[16][132];
    const int s0 = blockIdx.x * 128;
    const int c0 = blockIdx.y * 128;
    const int b  = blockIdx.z;
    const int t  = threadIdx.x;
    const int ty = t >> 4, tx = t & 15;          // 16 x 16
    const int m0 = ty * 8, n0 = tx * 8;

    const float* A = img + (size_t)b * CI * HW + s0;
    float acc[8][8];
#pragma unroll
    for (int i = 0; i < 8; i++)
#pragma unroll
        for (int j = 0; j < 8; j++) acc[i][j] = 0.f;

    for (int k0 = 0; k0 < CI; k0 += 16) {
#pragma unroll
        for (int it = 0; it < 2; it++) {
            const int idx = t + 256*it;
            const int kk = idx >> 5, col = (idx & 31) * 4;
            *(float4*)&As[kk][col] = *(const float4*)&A[(size_t)(k0+kk)*HW + col];
            *(float4*)&Bs[kk][col] = *(const float4*)&Wq[(size_t)(k0+kk)*CA + c0 + col];
        }
        __syncthreads();
#pragma unroll
        for (int kk = 0; kk < 16; kk++) {
            float4 a0 = *(float4*)&As[kk][m0];
            float4 a1 = *(float4*)&As[kk][m0+4];
            float4 b0 = *(float4*)&Bs[kk][n0];
            float4 b1 = *(float4*)&Bs[kk][n0+4];
            float a[8] = {a0.x,a0.y,a0.z,a0.w,a1.x,a1.y,a1.z,a1.w};
            float bb[8] = {b0.x,b0.y,b0.z,b0.w,b1.x,b1.y,b1.z,b1.w};
#pragma unroll
            for (int i = 0; i < 8; i++)
#pragma unroll
                for (int j = 0; j < 8; j++)
                    acc[i][j] = fmaf(a[i], bb[j], acc[i][j]);
        }
        __syncthreads();
    }
    float bias[8];
#pragma unroll
    for (int j = 0; j < 8; j++) bias[j] = bq[c0 + n0 + j];
#pragma unroll
    for (int i = 0; i < 8; i++) {
        const int s = s0 + m0 + i;
        float* o = &g_q[((size_t)b*HW + s)*CA + c0 + n0];
        float4 r0, r1;
        r0.x = (acc[i][0]+bias[0])*0.125f; r0.y = (acc[i][1]+bias[1])*0.125f;
        r0.z = (acc[i][2]+bias[2])*0.125f; r0.w = (acc[i][3]+bias[3])*0.125f;
        r1.x = (acc[i][4]+bias[4])*0.125f; r1.y = (acc[i][5]+bias[5])*0.125f;
        r1.z = (acc[i][6]+bias[6])*0.125f; r1.w = (acc[i][7]+bias[7])*0.125f;
        *(float4*)&o[0] = r0; *(float4*)&o[4] = r1;
    }
}

// ---------------------------------------------------------------------------
// K and V projections fused: 128x64 tile, 8x4 micro-tile x2 outputs.
// A = audio row-major [t, k]: transpose-on-load into As[kk][m].
// ---------------------------------------------------------------------------
__global__ void __launch_bounds__(256) gemm_kv_kernel(
    const float* __restrict__ aud,
    const float* __restrict__ Wk, const float* __restrict__ bk,
    const float* __restrict__ Wv, const float* __restrict__ bv)
{
    __shared__ float As[16][132];
    __shared__ float Bk[16][68];
    __shared__ float Bv[16][68];
    const int t0 = blockIdx.x * 128;
    const int c0 = blockIdx.y * 64;
    const int b  = blockIdx.z;
    const int t  = threadIdx.x;
    const int ty = t >> 4, tx = t & 15;
    const int m0 = ty * 8, n0 = tx * 4;

    const float* A = aud + (size_t)b * KL * CA;
    float ak[8][4], av[8][4];
#pragma unroll
    for (int i = 0; i < 8; i++)
#pragma unroll
        for (int j = 0; j < 4; j++) { ak[i][j] = 0.f; av[i][j] = 0.f; }

    for (int k0 = 0; k0 < CA; k0 += 16) {
        // A transpose-on-load: 128 m x 16 k = 512 float4
#pragma unroll
        for (int it = 0; it < 2; it++) {
            const int idx = t + 256*it;
            const int m = idx >> 2, kq = (idx & 3) * 4;
            float4 v = *(const float4*)&A[(size_t)(t0+m)*CA + k0 + kq];
            As[kq+0][m] = v.x; As[kq+1][m] = v.y; As[kq+2][m] = v.z; As[kq+3][m] = v.w;
        }
        {   // B tiles: 16 x 64 = 256 float4 each
            const int kk = t >> 4, col = (t & 15) * 4;
            *(float4*)&Bk[kk][col] = *(const float4*)&Wk[(size_t)(k0+kk)*CA + c0 + col];
            *(float4*)&Bv[kk][col] = *(const float4*)&Wv[(size_t)(k0+kk)*CA + c0 + col];
        }
        __syncthreads();
#pragma unroll
        for (int kk = 0; kk < 16; kk++) {
            float4 a0 = *(float4*)&As[kk][m0];
            float4 a1 = *(float4*)&As[kk][m0+4];
            float4 k4 = *(float4*)&Bk[kk][n0];
            float4 v4 = *(float4*)&Bv[kk][n0];
            float a[8] = {a0.x,a0.y,a0.z,a0.w,a1.x,a1.y,a1.z,a1.w};
            float kb[4] = {k4.x,k4.y,k4.z,k4.w};
            float vb[4] = {v4.x,v4.y,v4.z,v4.w};
#pragma unroll
            for (int i = 0; i < 8; i++)
#pragma unroll
                for (int j = 0; j < 4; j++) {
                    ak[i][j] = fmaf(a[i], kb[j], ak[i][j]);
                    av[i][j] = fmaf(a[i], vb[j], av[i][j]);
                }
        }
        __syncthreads();
    }
    float kbias[4], vbias[4];
#pragma unroll
    for (int j = 0; j < 4; j++) { kbias[j] = bk[c0+n0+j]; vbias[j] = bv[c0+n0+j]; }
#pragma unroll
    for (int i = 0; i < 8; i++) {
        const size_t row = ((size_t)b*KL + t0 + m0 + i)*CA + c0 + n0;
        float4 rk, rv;
        rk.x = ak[i][0]+kbias[0]; rk.y = ak[i][1]+kbias[1];
        rk.z = ak[i][2]+kbias[2]; rk.w = ak[i][3]+kbias[3];
        rv.x = av[i][0]+vbias[0]; rv.y = av[i][1]+vbias[1];
        rv.z = av[i][2]+vbias[2]; rv.w = av[i][3]+vbias[3];
        *(float4*)&g_k[row] = rk;
        *(float4*)&g_v[row] = rv;
    }
}

// ---------------------------------------------------------------------------
// Attention: one CTA per (b, h, 128-query tile). 256 threads.
// Scores: 4m x 8n micro-tile, Q^T and K^T k-major in smem (all LDS.128).
// Softmax in smem; PV: 4m x 8d micro-tile, V row-chunks in smem.
// ---------------------------------------------------------------------------
#define S_PAD   260
#define Q_PAD   132
#define KV_PAD  68
#define ATTN_SMEM_FLOATS (128*S_PAD + 64*Q_PAD + 64*KV_PAD)

__global__ void __launch_bounds__(256) attn_kernel()
{
    extern __shared__ float sm[];
    float* S  = sm;                       // [128][260]
    float* Qs = sm + 128*S_PAD;           // [64 d][132 m]   (k-major)
    float* Ks = Qs + 64*Q_PAD;            // [64 d][68 key]  / reused as Vs[64 key][68 d]

    const int s0 = blockIdx.x * 128;
    const int h  = blockIdx.y;
    const int b  = blockIdx.z;
    const int t  = threadIdx.x;
    const int ty = t >> 3, tx = t & 7;    // 32 x 8
    const int m0 = ty * 4, n0 = tx * 8;

    const float* qb = g_q + ((size_t)b*HW + s0)*CA + h*HD;
    const float* kb = g_k + (size_t)b*KL*CA + h*HD;
    const float* vb = g_v + (size_t)b*KL*CA + h*HD;

    // Load Q^T: 128 m x 64 d, transpose-on-load. 2048 float4.
#pragma unroll
    for (int it = 0; it < 8; it++) {
        const int idx = t + 256*it;
        const int r = idx >> 4, d4 = (idx & 15) * 4;
        float4 v = *(const float4*)&qb[(size_t)r*CA + d4];
        Qs[(d4+0)*Q_PAD + r] = v.x; Qs[(d4+1)*Q_PAD + r] = v.y;
        Qs[(d4+2)*Q_PAD + r] = v.z; Qs[(d4+3)*Q_PAD + r] = v.w;
    }

    // ---- scores S = Q K^T, key chunks of 64 ----
    for (int kc = 0; kc < 4; kc++) {
        __syncthreads();
#pragma unroll
        for (int it = 0; it < 4; it++) {
            const int idx = t + 256*it;
            const int key = idx >> 4, d4 = (idx & 15) * 4;
            float4 v = *(const float4*)&kb[(size_t)(kc*64 + key)*CA + d4];
            Ks[(d4+0)*KV_PAD + key] = v.x; Ks[(d4+1)*KV_PAD + key] = v.y;
            Ks[(d4+2)*KV_PAD + key] = v.z; Ks[(d4+3)*KV_PAD + key] = v.w;
        }
        __syncthreads();
        float acc[4][8];
#pragma unroll
        for (int i = 0; i < 4; i++)
#pragma unroll
            for (int j = 0; j < 8; j++) acc[i][j] = 0.f;
#pragma unroll 4
        for (int kk = 0; kk < 64; kk++) {
            float4 a4 = *(float4*)&Qs[kk*Q_PAD + m0];
            float4 b0 = *(float4*)&Ks[kk*KV_PAD + n0];
            float4 b1 = *(float4*)&Ks[kk*KV_PAD + n0 + 4];
            float a[4] = {a4.x,a4.y,a4.z,a4.w};
            float bb[8] = {b0.x,b0.y,b0.z,b0.w,b1.x,b1.y,b1.z,b1.w};
#pragma unroll
            for (int i = 0; i < 4; i++)
#pragma unroll
                for (int j = 0; j < 8; j++)
                    acc[i][j] = fmaf(a[i], bb[j], acc[i][j]);
        }
#pragma unroll
        for (int i = 0; i < 4; i++) {
            *(float4*)&S[(m0+i)*S_PAD + kc*64 + n0]     = *(float4*)&acc[i][0];
            *(float4*)&S[(m0+i)*S_PAD + kc*64 + n0 + 4] = *(float4*)&acc[i][4];
        }
    }
    __syncthreads();

    // ---- softmax over 256 keys, one warp per row ----
    {
        const int wid = t >> 5, lid = t & 31;
        for (int ri = 0; ri < 16; ri++) {
            const int r = wid*16 + ri;
            float vals[8];
            float m = -1e30f;
#pragma unroll
            for (int ii = 0; ii < 8; ii++) {
                vals[ii] = S[r*S_PAD + lid + 32*ii];
                m = fmaxf(m, vals[ii]);
            }
#pragma unroll
            for (int off = 16; off; off >>= 1) m = fmaxf(m, __shfl_xor_sync(0xffffffffu, m, off));
            float sum = 0.f;
#pragma unroll
            for (int ii = 0; ii < 8; ii++) { vals[ii] = __expf(vals[ii] - m); sum += vals[ii]; }
#pragma unroll
            for (int off = 16; off; off >>= 1) sum += __shfl_xor_sync(0xffffffffu, sum, off);
            const float inv = 1.f / sum;
#pragma unroll
            for (int ii = 0; ii < 8; ii++) S[r*S_PAD + lid + 32*ii] = vals[ii] * inv;
        }
    }

    // ---- O = P V ----  (n dim = d, k dim = key; V chunks row-major in smem)
    float oacc[4][8];
#pragma unroll
    for (int i = 0; i < 4; i++)
#pragma unroll
        for (int j = 0; j < 8; j++) oacc[i][j] = 0.f;

    for (int kc = 0; kc < 4; kc++) {
        __syncthreads();
#pragma unroll
        for (int it = 0; it < 4; it++) {
            const int idx = t + 256*it;
            const int key = idx >> 4, d4 = (idx & 15) * 4;
            *(float4*)&Ks[key*KV_PAD + d4] =
                *(const float4*)&vb[(size_t)(kc*64 + key)*CA + d4];
        }
        __syncthreads();
#pragma unroll 4
        for (int kk = 0; kk < 64; kk++) {
            float a[4];
#pragma unroll
            for (int i = 0; i < 4; i++) a[i] = S[(m0+i)*S_PAD + kc*64 + kk];
            float4 b0 = *(float4*)&Ks[kk*KV_PAD + n0];
            float4 b1 = *(float4*)&Ks[kk*KV_PAD + n0 + 4];
            float bb[8] = {b0.x,b0.y,b0.z,b0.w,b1.x,b1.y,b1.z,b1.w};
#pragma unroll
            for (int i = 0; i < 4; i++)
#pragma unroll
                for (int j = 0; j < 8; j++)
                    oacc[i][j] = fmaf(a[i], bb[j], oacc[i][j]);
        }
    }

    float* ob = g_attn + ((size_t)b*HW + s0)*CA + h*HD;
#pragma unroll
    for (int i = 0; i < 4; i++) {
        *(float4*)&ob[(size_t)(m0+i)*CA + n0]     = *(float4*)&oacc[i][0];
        *(float4*)&ob[(size_t)(m0+i)*CA + n0 + 4] = *(float4*)&oacc[i][4];
    }
}

// ---------------------------------------------------------------------------
// O projection + bias + residual: y[b,s,c] = attn[b,s,:]@Wo + bo + img[b,c,s]
// 128x128 tile, transpose-on-load A, residual read vectorized along s.
// ---------------------------------------------------------------------------
__global__ void __launch_bounds__(256) gemm_o_kernel(
    const float* __restrict__ img, const float* __restrict__ Wo,
    const float* __restrict__ bo)
{
    __shared__ float As[16][132];
    __shared__ float Bs[16][132];
    const int s0 = blockIdx.x * 128;
    const int c0 = blockIdx.y * 128;
    const int b  = blockIdx.z;
    const int t  = threadIdx.x;
    const int ty = t >> 4, tx = t & 15;
    const int m0 = ty * 8, n0 = tx * 8;

    const float* A = g_attn + (size_t)b * HW * CA;
    float acc[8][8];
#pragma unroll
    for (int i = 0; i < 8; i++)
#pragma unroll
        for (int j = 0; j < 8; j++) acc[i][j] = 0.f;

    for (int k0 = 0; k0 < CA; k0 += 16) {
#pragma unroll
        for (int it = 0; it < 2; it++) {
            const int idx = t + 256*it;
            const int m = idx >> 2, kq = (idx & 3) * 4;
            float4 v = *(const float4*)&A[(size_t)(s0+m)*CA + k0 + kq];
            As[kq+0][m] = v.x; As[kq+1][m] = v.y; As[kq+2][m] = v.z; As[kq+3][m] = v.w;
            const int kk = idx >> 5, col = (idx & 31) * 4;
            *(float4*)&Bs[kk][col] = *(const float4*)&Wo[(size_t)(k0+kk)*CI + c0 + col];
        }
        __syncthreads();
#pragma unroll
        for (int kk = 0; kk < 16; kk++) {
            float4 a0 = *(float4*)&As[kk][m0];
            float4 a1 = *(float4*)&As[kk][m0+4];
            float4 b0 = *(float4*)&Bs[kk][n0];
            float4 b1 = *(float4*)&Bs[kk][n0+4];
            float a[8] = {a0.x,a0.y,a0.z,a0.w,a1.x,a1.y,a1.z,a1.w};
            float bb[8] = {b0.x,b0.y,b0.z,b0.w,b1.x,b1.y,b1.z,b1.w};
#pragma unroll
            for (int i = 0; i < 8; i++)
#pragma unroll
                for (int j = 0; j < 8; j++)
                    acc[i][j] = fmaf(a[i], bb[j], acc[i][j]);
        }
        __syncthreads();
    }
    // residual: img[b][c][s], vectorized over s (i); bias
#pragma unroll
    for (int j = 0; j < 8; j++) {
        const int c = c0 + n0 + j;
        const float bias = bo[c];
        const float* rp = &img[(size_t)b*CI*HW + (size_t)c*HW + s0 + m0];
        float4 r0 = *(const float4*)&rp[0];
        float4 r1 = *(const float4*)&rp[4];
        float r[8] = {r0.x,r0.y,r0.z,r0.w,r1.x,r1.y,r1.z,r1.w};
#pragma unroll
        for (int i = 0; i < 8; i++) acc[i][j] += bias + r[i];
    }
#pragma unroll
    for (int i = 0; i < 8; i++) {
        float* o = &g_y[((size_t)b*HW + s0 + m0 + i)*CI + c0 + n0];
        *(float4*)&o[0] = *(float4*)&acc[i][0];
        *(float4*)&o[4] = *(float4*)&acc[i][4];
    }
}

// ---------------------------------------------------------------------------
// LayerNorm over channels + tiled transpose to [b, c, h*w].
// Block = (b, 32-row s chunk). 32x512 smem tile; coalesced in AND out.
// ---------------------------------------------------------------------------
#define LN_PAD 513
#define LN_SMEM_FLOATS (32*LN_PAD + 64)

__global__ void __launch_bounds__(256) ln_kernel(
    const float* __restrict__ gamma, const float* __restrict__ beta,
    float* __restrict__ out)
{
    extern __shared__ float sm[];
    float* tile = sm;                 // [32][513]
    float* s_mu  = sm + 32*LN_PAD;    // [32]
    float* s_inv = s_mu + 32;         // [32]

    const int s0 = blockIdx.x * 32;
    const int b  = blockIdx.y;
    const int t  = threadIdx.x;
    const float* yb = g_y + ((size_t)b*HW + s0) * CI;

    // load 32 x 512 (coalesced scalar; LN_PAD keeps transposed reads conflict-free)
#pragma unroll
    for (int it = 0; it < 64; it++) {
        const int idx = t + 256*it;
        const int si = idx >> 9, c = idx & 511;
        tile[si*LN_PAD + c] = yb[(size_t)si*CI + c];
    }
    __syncthreads();

    // per-row mean/var: warp w handles rows w*4 .. w*4+3
    {
        const int wid = t >> 5, lid = t & 31;
        for (int rr = 0; rr < 4; rr++) {
            const int si = wid*4 + rr;
            float sum = 0.f, sq = 0.f;
#pragma unroll
            for (int ii = 0; ii < 16; ii++) {
                float x = tile[si*LN_PAD + lid + 32*ii];
                sum += x; sq = fmaf(x, x, sq);
            }
#pragma unroll
            for (int off = 16; off; off >>= 1) {
                sum += __shfl_xor_sync(0xffffffffu, sum, off);
                sq  += __shfl_xor_sync(0xffffffffu, sq,  off);
            }
            if (lid == 0) {
                const float mu  = sum * (1.f/512.f);
                const float var = sq * (1.f/512.f) - mu*mu;
                s_mu[si] = mu;
                s_inv[si] = rsqrtf(var + 1e-5f);
            }
        }
    }
    __syncthreads();

    // transposed write: out[b][c][s0+si], lanes along si -> coalesced
#pragma unroll
    for (int it = 0; it < 64; it++) {
        const int idx = t + 256*it;
        const int c = idx >> 5, si = idx & 31;
        const float x = tile[si*LN_PAD + c];
        out[((size_t)b*CI + c)*HW + s0 + si] =
            (x - s_mu[si]) * s_inv[si] * gamma[c] + beta[c];
    }
}

// ---------------------------------------------------------------------------
extern "C" void kernel_launch(void* const* d_in, const int* in_sizes, int n_in,
                              void* d_out, int out_size)
{
    (void)in_sizes; (void)n_in; (void)out_size;
    const float* img   = (const float*)d_in[0];
    const float* aud   = (const float*)d_in[1];
    const float* Wq    = (const float*)d_in[2];
    const float* bq    = (const float*)d_in[3];
    const float* Wk    = (const float*)d_in[4];
    const float* bk    = (const float*)d_in[5];
    const float* Wv    = (const float*)d_in[6];
    const float* bv    = (const float*)d_in[7];
    const float* Wo    = (const float*)d_in[8];
    const float* bo    = (const float*)d_in[9];
    const float* gamma = (const float*)d_in[10];
    const float* beta  = (const float*)d_in[11];
    float* out = (float*)d_out;

    gemm_q_kernel<<<dim3(HW/128, CA/128, B_), 256>>>(img, Wq, bq);
    gemm_kv_kernel<<<dim3(KL/128, CA/64, B_), 256>>>(aud, Wk, bk, Wv, bv);

    const size_t attn_smem = (size_t)ATTN_SMEM_FLOATS * sizeof(float);
    cudaFuncSetAttribute(attn_kernel, cudaFuncAttributeMaxDynamicSharedMemorySize,
                         (int)attn_smem);
    attn_kernel<<<dim3(HW/128, NH, B_), 256, attn_smem>>>();

    gemm_o_kernel<<<dim3(HW/128, CI/128, B_), 256>>>(img, Wo, bo);

    const size_t ln_smem = (size_t)LN_SMEM_FLOATS * sizeof(float);
    cudaFuncSetAttribute(ln_kernel, cudaFuncAttributeMaxDynamicSharedMemorySize,
                         (int)ln_smem);
    ln_kernel<<<dim3(HW/32, B_), 256, ln_smem>>>(gamma, beta, out);
}

// round 5
// speedup vs baseline: 2.5678x; 1.4329x over previous
#include <cuda_runtime.h>
#include <cuda_bf16.h>
#include <cstdint>

#define B_  16
#define CI  512
#define HW  1024
#define CA  512
#define KL  256
#define NH  8
#define HD  64

// ---------------------------------------------------------------------------
// Scratch (__device__ globals; allocation-free)
// ---------------------------------------------------------------------------
__device__ float g_q[B_*HW*CA];
__device__ float g_k[B_*KL*CA];
__device__ float g_v[B_*KL*CA];
__device__ float g_y[B_*HW*CI];
__device__ __nv_bfloat16 g_imgT_hi[B_*HW*CI], g_imgT_lo[B_*HW*CI];   // [b][s][k]
__device__ __nv_bfloat16 g_aud_hi[B_*KL*CA],  g_aud_lo[B_*KL*CA];    // [b][t][k]
__device__ __nv_bfloat16 g_attn_hi[B_*HW*CA], g_attn_lo[B_*HW*CA];   // [b][s][k]
__device__ __nv_bfloat16 g_wt_hi[4*512*512],  g_wt_lo[4*512*512];    // [widx][c][k]

// ---------------------------------------------------------------------------
// PTX helpers (baseline PTX only: ldmatrix + mma.sync, no tcgen05)
// ---------------------------------------------------------------------------
__device__ __forceinline__ uint32_t smem_to_u32(const void* p) {
    uint32_t a;
    asm("{ .reg .u64 t; cvta.to.shared.u64 t, %1; cvt.u32.u64 %0, t; }" : "=r"(a) : "l"(p));
    return a;
}
#define LDSM_X4(r, addr) \
    asm volatile("ldmatrix.sync.aligned.m8n8.x4.shared.b16 {%0,%1,%2,%3}, [%4];" \
        : "=r"((r)[0]), "=r"((r)[1]), "=r"((r)[2]), "=r"((r)[3]) : "r"(addr))
#define MMA_BF16(d, a, b) \
    asm volatile("mma.sync.aligned.m16n8k16.row.col.f32.bf16.bf16.f32 " \
        "{%0,%1,%2,%3}, {%4,%5,%6,%7}, {%8,%9}, {%0,%1,%2,%3};" \
        : "+f"((d)[0]), "+f"((d)[1]), "+f"((d)[2]), "+f"((d)[3]) \
        : "r"((a)[0]), "r"((a)[1]), "r"((a)[2]), "r"((a)[3]), "r"((b)[0]), "r"((b)[1]))

__device__ __forceinline__ void split_bf16(float x, __nv_bfloat16& h, __nv_bfloat16& l) {
    h = __float2bfloat16(x);
    l = __float2bfloat16(x - __bfloat162float(h));
}
__device__ __forceinline__ unsigned pk2(__nv_bfloat16 a, __nv_bfloat16 b) {
    __nv_bfloat162 t = __halves2bfloat162(a, b);
    return *reinterpret_cast<unsigned*>(&t);
}

// ---------------------------------------------------------------------------
// Prep: W[k][c] -> Wt hi/lo [c][k] bf16 (4 matrices, z-indexed)
// ---------------------------------------------------------------------------
__global__ void __launch_bounds__(256) prep_w_kernel(
    const float* __restrict__ Wq, const float* __restrict__ Wk,
    const float* __restrict__ Wv, const float* __restrict__ Wo)
{
    const float* W = (blockIdx.z == 0) ? Wq : (blockIdx.z == 1) ? Wk
                   : (blockIdx.z == 2) ? Wv : Wo;
    __nv_bfloat16* oh = g_wt_hi + (size_t)blockIdx.z * 512 * 512;
    __nv_bfloat16* ol = g_wt_lo + (size_t)blockIdx.z * 512 * 512;
    __shared__ float tl[32][33];
    const int k0 = blockIdx.x * 32, c0 = blockIdx.y * 32;
    const int tx = threadIdx.x, ty = threadIdx.y;
#pragma unroll
    for (int i = 0; i < 4; i++)
        tl[ty + 8*i][tx] = W[(size_t)(k0 + ty + 8*i) * 512 + c0 + tx];
    __syncthreads();
#pragma unroll
    for (int i = 0; i < 4; i++) {
        const int r = ty + 8*i;
        const float v = tl[tx][r];
        __nv_bfloat16 h, l; split_bf16(v, h, l);
        oh[(size_t)(c0 + r) * 512 + k0 + tx] = h;
        ol[(size_t)(c0 + r) * 512 + k0 + tx] = l;
    }
}

// img [b][k][s] -> imgT hi/lo [b][s][k]
__global__ void __launch_bounds__(256) prep_img_kernel(const float* __restrict__ img)
{
    __shared__ float tl[32][33];
    const int s0 = blockIdx.x * 32, k0 = blockIdx.y * 32, b = blockIdx.z;
    const int tx = threadIdx.x, ty = threadIdx.y;
#pragma unroll
    for (int i = 0; i < 4; i++)
        tl[ty + 8*i][tx] = img[((size_t)b*CI + k0 + ty + 8*i) * HW + s0 + tx];
    __syncthreads();
#pragma unroll
    for (int i = 0; i < 4; i++) {
        const int r = ty + 8*i;                  // s-local
        const float v = tl[tx][r];               // img[k0+tx][s0+r]
        __nv_bfloat16 h, l; split_bf16(v, h, l);
        const size_t o = ((size_t)b*HW + s0 + r) * 512 + k0 + tx;
        g_imgT_hi[o] = h;
        g_imgT_lo[o] = l;
    }
}

// audio fp32 -> hi/lo bf16 (same layout)
__global__ void __launch_bounds__(256) prep_aud_kernel(const float* __restrict__ aud)
{
    const int i = blockIdx.x * 256 + threadIdx.x;     // quads
    float4 v = ((const float4*)aud)[i];
    __nv_bfloat16 h0,l0,h1,l1,h2,l2,h3,l3;
    split_bf16(v.x,h0,l0); split_bf16(v.y,h1,l1);
    split_bf16(v.z,h2,l2); split_bf16(v.w,h3,l3);
    ((uint2*)g_aud_hi)[i] = make_uint2(pk2(h0,h1), pk2(h2,h3));
    ((uint2*)g_aud_lo)[i] = make_uint2(pk2(l0,l1), pk2(l2,l3));
}

// ---------------------------------------------------------------------------
// mma.sync GEMM: D[m, n] = sum_k A[m,k] * Wt[n,k], fp32 via bf16-split (3 MMAs)
// CTA tile 128x128, 8 warps (4m x 2n), warp tile 32x64.
// K = 512 in 16 chunks of 32, double-buffered smem.
// MODE: 0=Q (scale 0.125 -> g_q), 1=K -> g_k, 2=V -> g_v, 3=O -> g_y
// ---------------------------------------------------------------------------
#define SM_BIAS    0
#define SM_TILES   512
#define ROW_B      80         // 32 bf16 (64B) + 16B pad -> conflict-free ldmatrix
#define TILE_B     (128*ROW_B)           // 10240
#define STAGE_B    (4*TILE_B)            // Ah, Al, Bh, Bl = 40960
#define GEMM_SMEM  (SM_TILES + 2*STAGE_B)

__device__ __forceinline__ void fill_tiles(char* dst, const char* Ah, const char* Al,
                                           const char* Bh, const char* Bl,
                                           int chunk, int t)
{
    const size_t kb = (size_t)chunk * 64;        // 32 bf16 = 64 bytes
    const char* srcs[4] = { Ah + kb, Al + kb, Bh + kb, Bl + kb };
#pragma unroll
    for (int w = 0; w < 4; w++) {
        const char* s = srcs[w];
        char* d = dst + w * TILE_B;
#pragma unroll
        for (int it = 0; it < 2; it++) {
            const int idx = t + 256 * it;
            const int row = idx >> 2, q = (idx & 3) * 16;
            *(uint4*)(d + row * ROW_B + q) = *(const uint4*)(s + (size_t)row * 1024 + q);
        }
    }
}

template<int MODE>
__global__ void __launch_bounds__(256) gemm_mma(const float* __restrict__ bias)
{
    extern __shared__ char smem[];
    const uint32_t su = smem_to_u32(smem);
    const int t = threadIdx.x, wid = t >> 5, lane = t & 31;
    const int warp_m = wid >> 1, warp_n = wid & 1;

    constexpr int   Mtot  = (MODE == 0 || MODE == 3) ? 1024 : 256;
    constexpr float SCALE = (MODE == 0) ? 0.125f : 1.0f;
    const __nv_bfloat16* Ah = (MODE == 0) ? g_imgT_hi : (MODE == 3) ? g_attn_hi : g_aud_hi;
    const __nv_bfloat16* Al = (MODE == 0) ? g_imgT_lo : (MODE == 3) ? g_attn_lo : g_aud_lo;
    float* out = (MODE == 0) ? g_q : (MODE == 1) ? g_k : (MODE == 2) ? g_v : g_y;

    const int m0 = blockIdx.x * 128, c0 = blockIdx.y * 128, b = blockIdx.z;

    float* sbias = (float*)(smem + SM_BIAS);
    if (t < 128) sbias[t] = bias[c0 + t];

    const char* Acta_h = (const char*)(Ah + ((size_t)b * Mtot + m0) * 512);
    const char* Acta_l = (const char*)(Al + ((size_t)b * Mtot + m0) * 512);
    const char* Bcta_h = (const char*)(g_wt_hi + (size_t)MODE * 512 * 512 + (size_t)c0 * 512);
    const char* Bcta_l = (const char*)(g_wt_lo + (size_t)MODE * 512 * 512 + (size_t)c0 * 512);

    float acc[2][8][4];
#pragma unroll
    for (int mt = 0; mt < 2; mt++)
#pragma unroll
        for (int nt = 0; nt < 8; nt++)
#pragma unroll
            for (int r = 0; r < 4; r++) acc[mt][nt][r] = 0.f;

    // lane-dependent ldmatrix address pieces
    const int a_row  = (lane & 15);              // within 16-row m tile
    const int a_koff = (lane >> 4) << 4;         // 0 or 16 bytes (k half)
    const int b_row  = (lane & 7) + ((lane >> 4) << 3);   // within 16-row n pair
    const int b_koff = ((lane >> 3) & 1) << 4;

    fill_tiles(smem + SM_TILES, Acta_h, Acta_l, Bcta_h, Bcta_l, 0, t);
    __syncthreads();

    for (int c = 0; c < 16; c++) {
        const int st = c & 1;
        if (c + 1 < 16)
            fill_tiles(smem + SM_TILES + (st ^ 1) * STAGE_B,
                       Acta_h, Acta_l, Bcta_h, Bcta_l, c + 1, t);

        const uint32_t sbase = su + SM_TILES + st * STAGE_B;
        const uint32_t aBase = sbase + (warp_m * 32 + a_row) * ROW_B + a_koff;
        const uint32_t bBase = sbase + 2 * TILE_B + (warp_n * 64 + b_row) * ROW_B + b_koff;

#pragma unroll
        for (int ks = 0; ks < 2; ks++) {          // two k16 steps per 32-chunk
            uint32_t afrag[2][2][4];              // [mtile][hi/lo][4]
#pragma unroll
            for (int mt = 0; mt < 2; mt++)
#pragma unroll
                for (int p = 0; p < 2; p++)
                    LDSM_X4(afrag[mt][p], aBase + p * TILE_B + mt * 16 * ROW_B + ks * 32);

            uint32_t bfrag[8][2][2];              // [ntile][hi/lo][2]
#pragma unroll
            for (int n2 = 0; n2 < 4; n2++)
#pragma unroll
                for (int p = 0; p < 2; p++) {
                    uint32_t r[4];
                    LDSM_X4(r, bBase + p * TILE_B + n2 * 16 * ROW_B + ks * 32);
                    bfrag[2*n2][p][0]   = r[0]; bfrag[2*n2][p][1]   = r[1];
                    bfrag[2*n2+1][p][0] = r[2]; bfrag[2*n2+1][p][1] = r[3];
                }

#pragma unroll
            for (int mt = 0; mt < 2; mt++)
#pragma unroll
                for (int nt = 0; nt < 8; nt++) {
                    MMA_BF16(acc[mt][nt], afrag[mt][0], bfrag[nt][0]);  // hi*hi
                    MMA_BF16(acc[mt][nt], afrag[mt][0], bfrag[nt][1]);  // hi*lo
                    MMA_BF16(acc[mt][nt], afrag[mt][1], bfrag[nt][0]);  // lo*hi
                }
        }
        __syncthreads();
    }

    // epilogue: bias + scale, float2 stores
    const int row_base = b * Mtot + m0 + warp_m * 32 + (lane >> 2);
    const int cl_base  = warp_n * 64 + (lane & 3) * 2;
#pragma unroll
    for (int mt = 0; mt < 2; mt++) {
#pragma unroll
        for (int nt = 0; nt < 8; nt++) {
            const int cl = cl_base + nt * 8;
            const float b0 = sbias[cl], b1 = sbias[cl + 1];
            float2 v0, v1;
            v0.x = (acc[mt][nt][0] + b0) * SCALE;
            v0.y = (acc[mt][nt][1] + b1) * SCALE;
            v1.x = (acc[mt][nt][2] + b0) * SCALE;
            v1.y = (acc[mt][nt][3] + b1) * SCALE;
            const int r0 = row_base + mt * 16;
            *(float2*)&out[(size_t)r0 * 512 + c0 + cl]       = v0;
            *(float2*)&out[(size_t)(r0 + 8) * 512 + c0 + cl] = v1;
        }
    }
}

// ---------------------------------------------------------------------------
// Attention (SIMT): one CTA per (b, h, 128-query tile). 256 threads.
// Epilogue writes bf16 hi/lo for the tensor-core O projection.
// ---------------------------------------------------------------------------
#define S_PAD   260
#define Q_PAD   132
#define KV_PAD  68
#define ATTN_SMEM_FLOATS (128*S_PAD + 64*Q_PAD + 64*KV_PAD)

__global__ void __launch_bounds__(256) attn_kernel()
{
    extern __shared__ float sm[];
    float* S  = sm;                       // [128][260]
    float* Qs = sm + 128*S_PAD;           // [64 d][132 m]
    float* Ks = Qs + 64*Q_PAD;            // [64 d][68 key] / reused as V rows

    const int s0 = blockIdx.x * 128;
    const int h  = blockIdx.y;
    const int b  = blockIdx.z;
    const int t  = threadIdx.x;
    const int ty = t >> 3, tx = t & 7;
    const int m0 = ty * 4, n0 = tx * 8;

    const float* qb = g_q + ((size_t)b*HW + s0)*CA + h*HD;
    const float* kb = g_k + (size_t)b*KL*CA + h*HD;
    const float* vb = g_v + (size_t)b*KL*CA + h*HD;

#pragma unroll
    for (int it = 0; it < 8; it++) {
        const int idx = t + 256*it;
        const int r = idx >> 4, d4 = (idx & 15) * 4;
        float4 v = *(const float4*)&qb[(size_t)r*CA + d4];
        Qs[(d4+0)*Q_PAD + r] = v.x; Qs[(d4+1)*Q_PAD + r] = v.y;
        Qs[(d4+2)*Q_PAD + r] = v.z; Qs[(d4+3)*Q_PAD + r] = v.w;
    }

    for (int kc = 0; kc < 4; kc++) {
        __syncthreads();
#pragma unroll
        for (int it = 0; it < 4; it++) {
            const int idx = t + 256*it;
            const int key = idx >> 4, d4 = (idx & 15) * 4;
            float4 v = *(const float4*)&kb[(size_t)(kc*64 + key)*CA + d4];
            Ks[(d4+0)*KV_PAD + key] = v.x; Ks[(d4+1)*KV_PAD + key] = v.y;
            Ks[(d4+2)*KV_PAD + key] = v.z; Ks[(d4+3)*KV_PAD + key] = v.w;
        }
        __syncthreads();
        float acc[4][8];
#pragma unroll
        for (int i = 0; i < 4; i++)
#pragma unroll
            for (int j = 0; j < 8; j++) acc[i][j] = 0.f;
#pragma unroll 4
        for (int kk = 0; kk < 64; kk++) {
            float4 a4 = *(float4*)&Qs[kk*Q_PAD + m0];
            float4 b0 = *(float4*)&Ks[kk*KV_PAD + n0];
            float4 b1 = *(float4*)&Ks[kk*KV_PAD + n0 + 4];
            float a[4] = {a4.x,a4.y,a4.z,a4.w};
            float bb[8] = {b0.x,b0.y,b0.z,b0.w,b1.x,b1.y,b1.z,b1.w};
#pragma unroll
            for (int i = 0; i < 4; i++)
#pragma unroll
                for (int j = 0; j < 8; j++)
                    acc[i][j] = fmaf(a[i], bb[j], acc[i][j]);
        }
#pragma unroll
        for (int i = 0; i < 4; i++) {
            *(float4*)&S[(m0+i)*S_PAD + kc*64 + n0]     = *(float4*)&acc[i][0];
            *(float4*)&S[(m0+i)*S_PAD + kc*64 + n0 + 4] = *(float4*)&acc[i][4];
        }
    }
    __syncthreads();

    {   // softmax, one warp per row
        const int wd = t >> 5, lid = t & 31;
        for (int ri = 0; ri < 16; ri++) {
            const int r = wd*16 + ri;
            float vals[8];
            float m = -1e30f;
#pragma unroll
            for (int ii = 0; ii < 8; ii++) {
                vals[ii] = S[r*S_PAD + lid + 32*ii];
                m = fmaxf(m, vals[ii]);
            }
#pragma unroll
            for (int off = 16; off; off >>= 1) m = fmaxf(m, __shfl_xor_sync(0xffffffffu, m, off));
            float sum = 0.f;
#pragma unroll
            for (int ii = 0; ii < 8; ii++) { vals[ii] = __expf(vals[ii] - m); sum += vals[ii]; }
#pragma unroll
            for (int off = 16; off; off >>= 1) sum += __shfl_xor_sync(0xffffffffu, sum, off);
            const float inv = 1.f / sum;
#pragma unroll
            for (int ii = 0; ii < 8; ii++) S[r*S_PAD + lid + 32*ii] = vals[ii] * inv;
        }
    }

    float oacc[4][8];
#pragma unroll
    for (int i = 0; i < 4; i++)
#pragma unroll
        for (int j = 0; j < 8; j++) oacc[i][j] = 0.f;

    for (int kc = 0; kc < 4; kc++) {
        __syncthreads();
#pragma unroll
        for (int it = 0; it < 4; it++) {
            const int idx = t + 256*it;
            const int key = idx >> 4, d4 = (idx & 15) * 4;
            *(float4*)&Ks[key*KV_PAD + d4] =
                *(const float4*)&vb[(size_t)(kc*64 + key)*CA + d4];
        }
        __syncthreads();
#pragma unroll 4
        for (int kk = 0; kk < 64; kk++) {
            float a[4];
#pragma unroll
            for (int i = 0; i < 4; i++) a[i] = S[(m0+i)*S_PAD + kc*64 + kk];
            float4 b0 = *(float4*)&Ks[kk*KV_PAD + n0];
            float4 b1 = *(float4*)&Ks[kk*KV_PAD + n0 + 4];
            float bb[8] = {b0.x,b0.y,b0.z,b0.w,b1.x,b1.y,b1.z,b1.w};
#pragma unroll
            for (int i = 0; i < 4; i++)
#pragma unroll
                for (int j = 0; j < 8; j++)
                    oacc[i][j] = fmaf(a[i], bb[j], oacc[i][j]);
        }
    }

    __nv_bfloat16* oh = g_attn_hi + ((size_t)b*HW + s0)*CA + h*HD;
    __nv_bfloat16* ol = g_attn_lo + ((size_t)b*HW + s0)*CA + h*HD;
#pragma unroll
    for (int i = 0; i < 4; i++) {
        unsigned hp[4], lp[4];
#pragma unroll
        for (int j2 = 0; j2 < 4; j2++) {
            __nv_bfloat16 h0, l0, h1, l1;
            split_bf16(oacc[i][2*j2],   h0, l0);
            split_bf16(oacc[i][2*j2+1], h1, l1);
            hp[j2] = pk2(h0, h1); lp[j2] = pk2(l0, l1);
        }
        *(uint4*)&oh[(size_t)(m0+i)*CA + n0] = make_uint4(hp[0], hp[1], hp[2], hp[3]);
        *(uint4*)&ol[(size_t)(m0+i)*CA + n0] = make_uint4(lp[0], lp[1], lp[2], lp[3]);
    }
}

// ---------------------------------------------------------------------------
// LayerNorm: y = proj + img (residual), normalize over c, transpose to NCHW
// ---------------------------------------------------------------------------
#define LN_PAD 513
#define LN_SMEM_FLOATS (32*LN_PAD + 64)

__global__ void __launch_bounds__(256) ln_kernel(
    const float* __restrict__ img,
    const float* __restrict__ gamma, const float* __restrict__ beta,
    float* __restrict__ out)
{
    extern __shared__ float sm[];
    float* tile = sm;                 // [32][513]
    float* s_mu  = sm + 32*LN_PAD;
    float* s_inv = s_mu + 32;

    const int s0 = blockIdx.x * 32;
    const int b  = blockIdx.y;
    const int t  = threadIdx.x;
    const float* yb = g_y + ((size_t)b*HW + s0) * CI;

#pragma unroll
    for (int it = 0; it < 64; it++) {
        const int idx = t + 256*it;
        const int si = idx >> 9, c = idx & 511;
        tile[si*LN_PAD + c] = yb[(size_t)si*CI + c];
    }
    __syncthreads();
    // residual: img[b][c][s0+si], si fast -> coalesced
#pragma unroll
    for (int it = 0; it < 64; it++) {
        const int idx = t + 256*it;
        const int c = idx >> 5, si = idx & 31;
        tile[si*LN_PAD + c] += img[((size_t)b*CI + c)*HW + s0 + si];
    }
    __syncthreads();

    {
        const int wd = t >> 5, lid = t & 31;
        for (int rr = 0; rr < 4; rr++) {
            const int si = wd*4 + rr;
            float sum = 0.f, sq = 0.f;
#pragma unroll
            for (int ii = 0; ii < 16; ii++) {
                float x = tile[si*LN_PAD + lid + 32*ii];
                sum += x; sq = fmaf(x, x, sq);
            }
#pragma unroll
            for (int off = 16; off; off >>= 1) {
                sum += __shfl_xor_sync(0xffffffffu, sum, off);
                sq  += __shfl_xor_sync(0xffffffffu, sq,  off);
            }
            if (lid == 0) {
                const float mu  = sum * (1.f/512.f);
                const float var = sq * (1.f/512.f) - mu*mu;
                s_mu[si] = mu;
                s_inv[si] = rsqrtf(var + 1e-5f);
            }
        }
    }
    __syncthreads();

#pragma unroll
    for (int it = 0; it < 64; it++) {
        const int idx = t + 256*it;
        const int c = idx >> 5, si = idx & 31;
        const float x = tile[si*LN_PAD + c];
        out[((size_t)b*CI + c)*HW + s0 + si] =
            (x - s_mu[si]) * s_inv[si] * gamma[c] + beta[c];
    }
}

// ---------------------------------------------------------------------------
extern "C" void kernel_launch(void* const* d_in, const int* in_sizes, int n_in,
                              void* d_out, int out_size)
{
    (void)in_sizes; (void)n_in; (void)out_size;
    const float* img   = (const float*)d_in[0];
    const float* aud   = (const float*)d_in[1];
    const float* Wq    = (const float*)d_in[2];
    const float* bq    = (const float*)d_in[3];
    const float* Wk    = (const float*)d_in[4];
    const float* bk    = (const float*)d_in[5];
    const float* Wv    = (const float*)d_in[6];
    const float* bv    = (const float*)d_in[7];
    const float* Wo    = (const float*)d_in[8];
    const float* bo    = (const float*)d_in[9];
    const float* gamma = (const float*)d_in[10];
    const float* beta  = (const float*)d_in[11];
    float* out = (float*)d_out;

    cudaFuncSetAttribute(gemm_mma<0>, cudaFuncAttributeMaxDynamicSharedMemorySize, GEMM_SMEM);
    cudaFuncSetAttribute(gemm_mma<1>, cudaFuncAttributeMaxDynamicSharedMemorySize, GEMM_SMEM);
    cudaFuncSetAttribute(gemm_mma<2>, cudaFuncAttributeMaxDynamicSharedMemorySize, GEMM_SMEM);
    cudaFuncSetAttribute(gemm_mma<3>, cudaFuncAttributeMaxDynamicSharedMemorySize, GEMM_SMEM);

    prep_w_kernel<<<dim3(16, 16, 4), dim3(32, 8)>>>(Wq, Wk, Wv, Wo);
    prep_img_kernel<<<dim3(32, 16, B_), dim3(32, 8)>>>(img);
    prep_aud_kernel<<<(B_*KL*CA/4)/256, 256>>>(aud);

    gemm_mma<0><<<dim3(8, 4, B_), 256, GEMM_SMEM>>>(bq);
    gemm_mma<1><<<dim3(2, 4, B_), 256, GEMM_SMEM>>>(bk);
    gemm_mma<2><<<dim3(2, 4, B_), 256, GEMM_SMEM>>>(bv);

    const size_t attn_smem = (size_t)ATTN_SMEM_FLOATS * sizeof(float);
    cudaFuncSetAttribute(attn_kernel, cudaFuncAttributeMaxDynamicSharedMemorySize, (int)attn_smem);
    attn_kernel<<<dim3(HW/128, NH, B_), 256, attn_smem>>>();

    gemm_mma<3><<<dim3(8, 4, B_), 256, GEMM_SMEM>>>(bo);

    const size_t ln_smem = (size_t)LN_SMEM_FLOATS * sizeof(float);
    cudaFuncSetAttribute(ln_kernel, cudaFuncAttributeMaxDynamicSharedMemorySize, (int)ln_smem);
    ln_kernel<<<dim3(HW/32, B_), 256, ln_smem>>>(img, gamma, beta, out);
}

// round 6
// speedup vs baseline: 2.5693x; 1.0006x over previous
#include <cuda_runtime.h>
#include <cuda_bf16.h>
#include <cstdint>

#define B_  16
#define CI  512
#define HW  1024
#define CA  512
#define KL  256
#define NH  8
#define HD  64

// ---------------------------------------------------------------------------
// Scratch (__device__ globals; allocation-free)
// ---------------------------------------------------------------------------
__device__ float g_q[B_*HW*CA];
__device__ float g_k[B_*KL*CA];
__device__ float g_v[B_*KL*CA];
__device__ float g_y[B_*HW*CI];
__device__ __nv_bfloat16 g_imgT_hi[B_*HW*CI], g_imgT_lo[B_*HW*CI];   // [b][s][k]
__device__ __nv_bfloat16 g_aud_hi[B_*KL*CA],  g_aud_lo[B_*KL*CA];    // [b][t][k]
__device__ __nv_bfloat16 g_attn_hi[B_*HW*CA], g_attn_lo[B_*HW*CA];   // [b][s][k]
__device__ __nv_bfloat16 g_wt_hi[4*512*512],  g_wt_lo[4*512*512];    // [widx][c][k]

// ---------------------------------------------------------------------------
// PTX helpers (baseline PTX only: ldmatrix + mma.sync, no tcgen05)
// ---------------------------------------------------------------------------
__device__ __forceinline__ uint32_t smem_to_u32(const void* p) {
    uint32_t a;
    asm("{ .reg .u64 t; cvta.to.shared.u64 t, %1; cvt.u32.u64 %0, t; }" : "=r"(a) : "l"(p));
    return a;
}
#define LDSM_X4(r, addr) \
    asm volatile("ldmatrix.sync.aligned.m8n8.x4.shared.b16 {%0,%1,%2,%3}, [%4];" \
        : "=r"((r)[0]), "=r"((r)[1]), "=r"((r)[2]), "=r"((r)[3]) : "r"(addr))
#define MMA_BF16(d, a, b) \
    asm volatile("mma.sync.aligned.m16n8k16.row.col.f32.bf16.bf16.f32 " \
        "{%0,%1,%2,%3}, {%4,%5,%6,%7}, {%8,%9}, {%0,%1,%2,%3};" \
        : "+f"((d)[0]), "+f"((d)[1]), "+f"((d)[2]), "+f"((d)[3]) \
        : "r"((a)[0]), "r"((a)[1]), "r"((a)[2]), "r"((a)[3]), "r"((b)[0]), "r"((b)[1]))

__device__ __forceinline__ void split_bf16(float x, __nv_bfloat16& h, __nv_bfloat16& l) {
    h = __float2bfloat16(x);
    l = __float2bfloat16(x - __bfloat162float(h));
}
__device__ __forceinline__ unsigned pk2(__nv_bfloat16 a, __nv_bfloat16 b) {
    __nv_bfloat162 t = __halves2bfloat162(a, b);
    return *reinterpret_cast<unsigned*>(&t);
}

// ---------------------------------------------------------------------------
// Prep: W[k][c] -> Wt hi/lo [c][k] bf16 (4 matrices, z-indexed)
// ---------------------------------------------------------------------------
__global__ void __launch_bounds__(256) prep_w_kernel(
    const float* __restrict__ Wq, const float* __restrict__ Wk,
    const float* __restrict__ Wv, const float* __restrict__ Wo)
{
    const float* W = (blockIdx.z == 0) ? Wq : (blockIdx.z == 1) ? Wk
                   : (blockIdx.z == 2) ? Wv : Wo;
    __nv_bfloat16* oh = g_wt_hi + (size_t)blockIdx.z * 512 * 512;
    __nv_bfloat16* ol = g_wt_lo + (size_t)blockIdx.z * 512 * 512;
    __shared__ float tl[32][33];
    const int k0 = blockIdx.x * 32, c0 = blockIdx.y * 32;
    const int tx = threadIdx.x, ty = threadIdx.y;
#pragma unroll
    for (int i = 0; i < 4; i++)
        tl[ty + 8*i][tx] = W[(size_t)(k0 + ty + 8*i) * 512 + c0 + tx];
    __syncthreads();
#pragma unroll
    for (int i = 0; i < 4; i++) {
        const int r = ty + 8*i;
        const float v = tl[tx][r];
        __nv_bfloat16 h, l; split_bf16(v, h, l);
        oh[(size_t)(c0 + r) * 512 + k0 + tx] = h;
        ol[(size_t)(c0 + r) * 512 + k0 + tx] = l;
    }
}

// img [b][k][s] -> imgT hi/lo [b][s][k]
__global__ void __launch_bounds__(256) prep_img_kernel(const float* __restrict__ img)
{
    __shared__ float tl[32][33];
    const int s0 = blockIdx.x * 32, k0 = blockIdx.y * 32, b = blockIdx.z;
    const int tx = threadIdx.x, ty = threadIdx.y;
#pragma unroll
    for (int i = 0; i < 4; i++)
        tl[ty + 8*i][tx] = img[((size_t)b*CI + k0 + ty + 8*i) * HW + s0 + tx];
    __syncthreads();
#pragma unroll
    for (int i = 0; i < 4; i++) {
        const int r = ty + 8*i;                  // s-local
        const float v = tl[tx][r];               // img[k0+tx][s0+r]
        __nv_bfloat16 h, l; split_bf16(v, h, l);
        const size_t o = ((size_t)b*HW + s0 + r) * 512 + k0 + tx;
        g_imgT_hi[o] = h;
        g_imgT_lo[o] = l;
    }
}

// audio fp32 -> hi/lo bf16 (same layout)
__global__ void __launch_bounds__(256) prep_aud_kernel(const float* __restrict__ aud)
{
    const int i = blockIdx.x * 256 + threadIdx.x;     // quads
    float4 v = ((const float4*)aud)[i];
    __nv_bfloat16 h0,l0,h1,l1,h2,l2,h3,l3;
    split_bf16(v.x,h0,l0); split_bf16(v.y,h1,l1);
    split_bf16(v.z,h2,l2); split_bf16(v.w,h3,l3);
    ((uint2*)g_aud_hi)[i] = make_uint2(pk2(h0,h1), pk2(h2,h3));
    ((uint2*)g_aud_lo)[i] = make_uint2(pk2(l0,l1), pk2(l2,l3));
}

// ---------------------------------------------------------------------------
// mma.sync GEMM: D[m, n] = sum_k A[m,k] * Wt[n,k], fp32 via bf16-split (3 MMAs)
// CTA tile 128x128, 8 warps (4m x 2n), warp tile 32x64.
// K = 512 in 16 chunks of 32, double-buffered smem.
// MODE: 0=Q (scale 0.125 -> g_q), 1=K -> g_k, 2=V -> g_v, 3=O -> g_y
// ---------------------------------------------------------------------------
#define SM_BIAS    0
#define SM_TILES   512
#define ROW_B      80         // 32 bf16 (64B) + 16B pad -> conflict-free ldmatrix
#define TILE_B     (128*ROW_B)           // 10240
#define STAGE_B    (4*TILE_B)            // Ah, Al, Bh, Bl = 40960
#define GEMM_SMEM  (SM_TILES + 2*STAGE_B)

__device__ __forceinline__ void fill_tiles(char* dst, const char* Ah, const char* Al,
                                           const char* Bh, const char* Bl,
                                           int chunk, int t)
{
    const size_t kb = (size_t)chunk * 64;        // 32 bf16 = 64 bytes
    const char* srcs[4] = { Ah + kb, Al + kb, Bh + kb, Bl + kb };
#pragma unroll
    for (int w = 0; w < 4; w++) {
        const char* s = srcs[w];
        char* d = dst + w * TILE_B;
#pragma unroll
        for (int it = 0; it < 2; it++) {
            const int idx = t + 256 * it;
            const int row = idx >> 2, q = (idx & 3) * 16;
            *(uint4*)(d + row * ROW_B + q) = *(const uint4*)(s + (size_t)row * 1024 + q);
        }
    }
}

template<int MODE>
__global__ void __launch_bounds__(256) gemm_mma(const float* __restrict__ bias)
{
    extern __shared__ char smem[];
    const uint32_t su = smem_to_u32(smem);
    const int t = threadIdx.x, wid = t >> 5, lane = t & 31;
    const int warp_m = wid >> 1, warp_n = wid & 1;

    constexpr int   Mtot  = (MODE == 0 || MODE == 3) ? 1024 : 256;
    constexpr float SCALE = (MODE == 0) ? 0.125f : 1.0f;
    const __nv_bfloat16* Ah = (MODE == 0) ? g_imgT_hi : (MODE == 3) ? g_attn_hi : g_aud_hi;
    const __nv_bfloat16* Al = (MODE == 0) ? g_imgT_lo : (MODE == 3) ? g_attn_lo : g_aud_lo;
    float* out = (MODE == 0) ? g_q : (MODE == 1) ? g_k : (MODE == 2) ? g_v : g_y;

    const int m0 = blockIdx.x * 128, c0 = blockIdx.y * 128, b = blockIdx.z;

    float* sbias = (float*)(smem + SM_BIAS);
    if (t < 128) sbias[t] = bias[c0 + t];

    const char* Acta_h = (const char*)(Ah + ((size_t)b * Mtot + m0) * 512);
    const char* Acta_l = (const char*)(Al + ((size_t)b * Mtot + m0) * 512);
    const char* Bcta_h = (const char*)(g_wt_hi + (size_t)MODE * 512 * 512 + (size_t)c0 * 512);
    const char* Bcta_l = (const char*)(g_wt_lo + (size_t)MODE * 512 * 512 + (size_t)c0 * 512);

    float acc[2][8][4];
#pragma unroll
    for (int mt = 0; mt < 2; mt++)
#pragma unroll
        for (int nt = 0; nt < 8; nt++)
#pragma unroll
            for (int r = 0; r < 4; r++) acc[mt][nt][r] = 0.f;

    // lane-dependent ldmatrix address pieces
    const int a_row  = (lane & 15);              // within 16-row m tile
    const int a_koff = (lane >> 4) << 4;         // 0 or 16 bytes (k half)
    const int b_row  = (lane & 7) + ((lane >> 4) << 3);   // within 16-row n pair
    const int b_koff = ((lane >> 3) & 1) << 4;

    fill_tiles(smem + SM_TILES, Acta_h, Acta_l, Bcta_h, Bcta_l, 0, t);
    __syncthreads();

    for (int c = 0; c < 16; c++) {
        const int st = c & 1;
        if (c + 1 < 16)
            fill_tiles(smem + SM_TILES + (st ^ 1) * STAGE_B,
                       Acta_h, Acta_l, Bcta_h, Bcta_l, c + 1, t);

        const uint32_t sbase = su + SM_TILES + st * STAGE_B;
        const uint32_t aBase = sbase + (warp_m * 32 + a_row) * ROW_B + a_koff;
        const uint32_t bBase = sbase + 2 * TILE_B + (warp_n * 64 + b_row) * ROW_B + b_koff;

#pragma unroll
        for (int ks = 0; ks < 2; ks++) {          // two k16 steps per 32-chunk
            uint32_t afrag[2][2][4];              // [mtile][hi/lo][4]
#pragma unroll
            for (int mt = 0; mt < 2; mt++)
#pragma unroll
                for (int p = 0; p < 2; p++)
                    LDSM_X4(afrag[mt][p], aBase + p * TILE_B + mt * 16 * ROW_B + ks * 32);

            uint32_t bfrag[8][2][2];              // [ntile][hi/lo][2]
#pragma unroll
            for (int n2 = 0; n2 < 4; n2++)
#pragma unroll
                for (int p = 0; p < 2; p++) {
                    uint32_t r[4];
                    LDSM_X4(r, bBase + p * TILE_B + n2 * 16 * ROW_B + ks * 32);
                    bfrag[2*n2][p][0]   = r[0]; bfrag[2*n2][p][1]   = r[1];
                    bfrag[2*n2+1][p][0] = r[2]; bfrag[2*n2+1][p][1] = r[3];
                }

#pragma unroll
            for (int mt = 0; mt < 2; mt++)
#pragma unroll
                for (int nt = 0; nt < 8; nt++) {
                    MMA_BF16(acc[mt][nt], afrag[mt][0], bfrag[nt][0]);  // hi*hi
                    MMA_BF16(acc[mt][nt], afrag[mt][0], bfrag[nt][1]);  // hi*lo
                    MMA_BF16(acc[mt][nt], afrag[mt][1], bfrag[nt][0]);  // lo*hi
                }
        }
        __syncthreads();
    }

    // epilogue: bias + scale, float2 stores
    const int row_base = b * Mtot + m0 + warp_m * 32 + (lane >> 2);
    const int cl_base  = warp_n * 64 + (lane & 3) * 2;
#pragma unroll
    for (int mt = 0; mt < 2; mt++) {
#pragma unroll
        for (int nt = 0; nt < 8; nt++) {
            const int cl = cl_base + nt * 8;
            const float b0 = sbias[cl], b1 = sbias[cl + 1];
            float2 v0, v1;
            v0.x = (acc[mt][nt][0] + b0) * SCALE;
            v0.y = (acc[mt][nt][1] + b1) * SCALE;
            v1.x = (acc[mt][nt][2] + b0) * SCALE;
            v1.y = (acc[mt][nt][3] + b1) * SCALE;
            const int r0 = row_base + mt * 16;
            *(float2*)&out[(size_t)r0 * 512 + c0 + cl]       = v0;
            *(float2*)&out[(size_t)(r0 + 8) * 512 + c0 + cl] = v1;
        }
    }
}

// ---------------------------------------------------------------------------
// Attention (SIMT): one CTA per (b, h, 128-query tile). 256 threads.
// Epilogue writes bf16 hi/lo for the tensor-core O projection.
// ---------------------------------------------------------------------------
#define S_PAD   260
#define Q_PAD   132
#define KV_PAD  68
#define ATTN_SMEM_FLOATS (128*S_PAD + 64*Q_PAD + 64*KV_PAD)

__global__ void __launch_bounds__(256) attn_kernel()
{
    extern __shared__ float sm[];
    float* S  = sm;                       // [128][260]
    float* Qs = sm + 128*S_PAD;           // [64 d][132 m]
    float* Ks = Qs + 64*Q_PAD;            // [64 d][68 key] / reused as V rows

    const int s0 = blockIdx.x * 128;
    const int h  = blockIdx.y;
    const int b  = blockIdx.z;
    const int t  = threadIdx.x;
    const int ty = t >> 3, tx = t & 7;
    const int m0 = ty * 4, n0 = tx * 8;

    const float* qb = g_q + ((size_t)b*HW + s0)*CA + h*HD;
    const float* kb = g_k + (size_t)b*KL*CA + h*HD;
    const float* vb = g_v + (size_t)b*KL*CA + h*HD;

#pragma unroll
    for (int it = 0; it < 8; it++) {
        const int idx = t + 256*it;
        const int r = idx >> 4, d4 = (idx & 15) * 4;
        float4 v = *(const float4*)&qb[(size_t)r*CA + d4];
        Qs[(d4+0)*Q_PAD + r] = v.x; Qs[(d4+1)*Q_PAD + r] = v.y;
        Qs[(d4+2)*Q_PAD + r] = v.z; Qs[(d4+3)*Q_PAD + r] = v.w;
    }

    for (int kc = 0; kc < 4; kc++) {
        __syncthreads();
#pragma unroll
        for (int it = 0; it < 4; it++) {
            const int idx = t + 256*it;
            const int key = idx >> 4, d4 = (idx & 15) * 4;
            float4 v = *(const float4*)&kb[(size_t)(kc*64 + key)*CA + d4];
            Ks[(d4+0)*KV_PAD + key] = v.x; Ks[(d4+1)*KV_PAD + key] = v.y;
            Ks[(d4+2)*KV_PAD + key] = v.z; Ks[(d4+3)*KV_PAD + key] = v.w;
        }
        __syncthreads();
        float acc[4][8];
#pragma unroll
        for (int i = 0; i < 4; i++)
#pragma unroll
            for (int j = 0; j < 8; j++) acc[i][j] = 0.f;
#pragma unroll 4
        for (int kk = 0; kk < 64; kk++) {
            float4 a4 = *(float4*)&Qs[kk*Q_PAD + m0];
            float4 b0 = *(float4*)&Ks[kk*KV_PAD + n0];
            float4 b1 = *(float4*)&Ks[kk*KV_PAD + n0 + 4];
            float a[4] = {a4.x,a4.y,a4.z,a4.w};
            float bb[8] = {b0.x,b0.y,b0.z,b0.w,b1.x,b1.y,b1.z,b1.w};
#pragma unroll
            for (int i = 0; i < 4; i++)
#pragma unroll
                for (int j = 0; j < 8; j++)
                    acc[i][j] = fmaf(a[i], bb[j], acc[i][j]);
        }
#pragma unroll
        for (int i = 0; i < 4; i++) {
            *(float4*)&S[(m0+i)*S_PAD + kc*64 + n0]     = *(float4*)&acc[i][0];
            *(float4*)&S[(m0+i)*S_PAD + kc*64 + n0 + 4] = *(float4*)&acc[i][4];
        }
    }
    __syncthreads();

    {   // softmax, one warp per row
        const int wd = t >> 5, lid = t & 31;
        for (int ri = 0; ri < 16; ri++) {
            const int r = wd*16 + ri;
            float vals[8];
            float m = -1e30f;
#pragma unroll
            for (int ii = 0; ii < 8; ii++) {
                vals[ii] = S[r*S_PAD + lid + 32*ii];
                m = fmaxf(m, vals[ii]);
            }
#pragma unroll
            for (int off = 16; off; off >>= 1) m = fmaxf(m, __shfl_xor_sync(0xffffffffu, m, off));
            float sum = 0.f;
#pragma unroll
            for (int ii = 0; ii < 8; ii++) { vals[ii] = __expf(vals[ii] - m); sum += vals[ii]; }
#pragma unroll
            for (int off = 16; off; off >>= 1) sum += __shfl_xor_sync(0xffffffffu, sum, off);
            const float inv = 1.f / sum;
#pragma unroll
            for (int ii = 0; ii < 8; ii++) S[r*S_PAD + lid + 32*ii] = vals[ii] * inv;
        }
    }

    float oacc[4][8];
#pragma unroll
    for (int i = 0; i < 4; i++)
#pragma unroll
        for (int j = 0; j < 8; j++) oacc[i][j] = 0.f;

    for (int kc = 0; kc < 4; kc++) {
        __syncthreads();
#pragma unroll
        for (int it = 0; it < 4; it++) {
            const int idx = t + 256*it;
            const int key = idx >> 4, d4 = (idx & 15) * 4;
            *(float4*)&Ks[key*KV_PAD + d4] =
                *(const float4*)&vb[(size_t)(kc*64 + key)*CA + d4];
        }
        __syncthreads();
#pragma unroll 4
        for (int kk = 0; kk < 64; kk++) {
            float a[4];
#pragma unroll
            for (int i = 0; i < 4; i++) a[i] = S[(m0+i)*S_PAD + kc*64 + kk];
            float4 b0 = *(float4*)&Ks[kk*KV_PAD + n0];
            float4 b1 = *(float4*)&Ks[kk*KV_PAD + n0 + 4];
            float bb[8] = {b0.x,b0.y,b0.z,b0.w,b1.x,b1.y,b1.z,b1.w};
#pragma unroll
            for (int i = 0; i < 4; i++)
#pragma unroll
                for (int j = 0; j < 8; j++)
                    oacc[i][j] = fmaf(a[i], bb[j], oacc[i][j]);
        }
    }

    __nv_bfloat16* oh = g_attn_hi + ((size_t)b*HW + s0)*CA + h*HD;
    __nv_bfloat16* ol = g_attn_lo + ((size_t)b*HW + s0)*CA + h*HD;
#pragma unroll
    for (int i = 0; i < 4; i++) {
        unsigned hp[4], lp[4];
#pragma unroll
        for (int j2 = 0; j2 < 4; j2++) {
            __nv_bfloat16 h0, l0, h1, l1;
            split_bf16(oacc[i][2*j2],   h0, l0);
            split_bf16(oacc[i][2*j2+1], h1, l1);
            hp[j2] = pk2(h0, h1); lp[j2] = pk2(l0, l1);
        }
        *(uint4*)&oh[(size_t)(m0+i)*CA + n0] = make_uint4(hp[0], hp[1], hp[2], hp[3]);
        *(uint4*)&ol[(size_t)(m0+i)*CA + n0] = make_uint4(lp[0], lp[1], lp[2], lp[3]);
    }
}

// ---------------------------------------------------------------------------
// LayerNorm: y = proj + img (residual), normalize over c, transpose to NCHW
// ---------------------------------------------------------------------------
#define LN_PAD 513
#define LN_SMEM_FLOATS (32*LN_PAD + 64)

__global__ void __launch_bounds__(256) ln_kernel(
    const float* __restrict__ img,
    const float* __restrict__ gamma, const float* __restrict__ beta,
    float* __restrict__ out)
{
    extern __shared__ float sm[];
    float* tile = sm;                 // [32][513]
    float* s_mu  = sm + 32*LN_PAD;
    float* s_inv = s_mu + 32;

    const int s0 = blockIdx.x * 32;
    const int b  = blockIdx.y;
    const int t  = threadIdx.x;
    const float* yb = g_y + ((size_t)b*HW + s0) * CI;

#pragma unroll
    for (int it = 0; it < 64; it++) {
        const int idx = t + 256*it;
        const int si = idx >> 9, c = idx & 511;
        tile[si*LN_PAD + c] = yb[(size_t)si*CI + c];
    }
    __syncthreads();
    // residual: img[b][c][s0+si], si fast -> coalesced
#pragma unroll
    for (int it = 0; it < 64; it++) {
        const int idx = t + 256*it;
        const int c = idx >> 5, si = idx & 31;
        tile[si*LN_PAD + c] += img[((size_t)b*CI + c)*HW + s0 + si];
    }
    __syncthreads();

    {
        const int wd = t >> 5, lid = t & 31;
        for (int rr = 0; rr < 4; rr++) {
            const int si = wd*4 + rr;
            float sum = 0.f, sq = 0.f;
#pragma unroll
            for (int ii = 0; ii < 16; ii++) {
                float x = tile[si*LN_PAD + lid + 32*ii];
                sum += x; sq = fmaf(x, x, sq);
            }
#pragma unroll
            for (int off = 16; off; off >>= 1) {
                sum += __shfl_xor_sync(0xffffffffu, sum, off);
                sq  += __shfl_xor_sync(0xffffffffu, sq,  off);
            }
            if (lid == 0) {
                const float mu  = sum * (1.f/512.f);
                const float var = sq * (1.f/512.f) - mu*mu;
                s_mu[si] = mu;
                s_inv[si] = rsqrtf(var + 1e-5f);
            }
        }
    }
    __syncthreads();

#pragma unroll
    for (int it = 0; it < 64; it++) {
        const int idx = t + 256*it;
        const int c = idx >> 5, si = idx & 31;
        const float x = tile[si*LN_PAD + c];
        out[((size_t)b*CI + c)*HW + s0 + si] =
            (x - s_mu[si]) * s_inv[si] * gamma[c] + beta[c];
    }
}

// ---------------------------------------------------------------------------
extern "C" void kernel_launch(void* const* d_in, const int* in_sizes, int n_in,
                              void* d_out, int out_size)
{
    (void)in_sizes; (void)n_in; (void)out_size;
    const float* img   = (const float*)d_in[0];
    const float* aud   = (const float*)d_in[1];
    const float* Wq    = (const float*)d_in[2];
    const float* bq    = (const float*)d_in[3];
    const float* Wk    = (const float*)d_in[4];
    const float* bk    = (const float*)d_in[5];
    const float* Wv    = (const float*)d_in[6];
    const float* bv    = (const float*)d_in[7];
    const float* Wo    = (const float*)d_in[8];
    const float* bo    = (const float*)d_in[9];
    const float* gamma = (const float*)d_in[10];
    const float* beta  = (const float*)d_in[11];
    float* out = (float*)d_out;

    cudaFuncSetAttribute(gemm_mma<0>, cudaFuncAttributeMaxDynamicSharedMemorySize, GEMM_SMEM);
    cudaFuncSetAttribute(gemm_mma<1>, cudaFuncAttributeMaxDynamicSharedMemorySize, GEMM_SMEM);
    cudaFuncSetAttribute(gemm_mma<2>, cudaFuncAttributeMaxDynamicSharedMemorySize, GEMM_SMEM);
    cudaFuncSetAttribute(gemm_mma<3>, cudaFuncAttributeMaxDynamicSharedMemorySize, GEMM_SMEM);

    prep_w_kernel<<<dim3(16, 16, 4), dim3(32, 8)>>>(Wq, Wk, Wv, Wo);
    prep_img_kernel<<<dim3(32, 16, B_), dim3(32, 8)>>>(img);
    prep_aud_kernel<<<(B_*KL*CA/4)/256, 256>>>(aud);

    gemm_mma<0><<<dim3(8, 4, B_), 256, GEMM_SMEM>>>(bq);
    gemm_mma<1><<<dim3(2, 4, B_), 256, GEMM_SMEM>>>(bk);
    gemm_mma<2><<<dim3(2, 4, B_), 256, GEMM_SMEM>>>(bv);

    const size_t attn_smem = (size_t)ATTN_SMEM_FLOATS * sizeof(float);
    cudaFuncSetAttribute(attn_kernel, cudaFuncAttributeMaxDynamicSharedMemorySize, (int)attn_smem);
    attn_kernel<<<dim3(HW/128, NH, B_), 256, attn_smem>>>();

    gemm_mma<3><<<dim3(8, 4, B_), 256, GEMM_SMEM>>>(bo);

    const size_t ln_smem = (size_t)LN_SMEM_FLOATS * sizeof(float);
    cudaFuncSetAttribute(ln_kernel, cudaFuncAttributeMaxDynamicSharedMemorySize, (int)ln_smem);
    ln_kernel<<<dim3(HW/32, B_), 256, ln_smem>>>(img, gamma, beta, out);
}

// round 7
// speedup vs baseline: 3.7160x; 1.4463x over previous
#include <cuda_runtime.h>
#include <cuda_bf16.h>
#include <cstdint>

#define B_  16
#define CI  512
#define HW  1024
#define CA  512
#define KL  256
#define NH  8
#define HD  64

// ---------------------------------------------------------------------------
// Scratch (__device__ globals; allocation-free)
// ---------------------------------------------------------------------------
__device__ float g_q[B_*HW*CA];
__device__ float g_k[B_*KL*CA];
__device__ float g_v[B_*KL*CA];
__device__ float g_y[B_*HW*CI];
__device__ __nv_bfloat16 g_imgT_hi[B_*HW*CI], g_imgT_lo[B_*HW*CI];   // [b][s][k]
__device__ __nv_bfloat16 g_aud_hi[B_*KL*CA],  g_aud_lo[B_*KL*CA];    // [b][t][k]
__device__ __nv_bfloat16 g_attn_hi[B_*HW*CA], g_attn_lo[B_*HW*CA];   // [b][s][k]
__device__ __nv_bfloat16 g_wt_hi[4*512*512],  g_wt_lo[4*512*512];    // [widx][c][k]

// ---------------------------------------------------------------------------
// PTX helpers (baseline PTX only: ldmatrix + mma.sync)
// ---------------------------------------------------------------------------
__device__ __forceinline__ uint32_t smem_to_u32(const void* p) {
    uint32_t a;
    asm("{ .reg .u64 t; cvta.to.shared.u64 t, %1; cvt.u32.u64 %0, t; }" : "=r"(a) : "l"(p));
    return a;
}
#define LDSM_X4(r, addr) \
    asm volatile("ldmatrix.sync.aligned.m8n8.x4.shared.b16 {%0,%1,%2,%3}, [%4];" \
        : "=r"((r)[0]), "=r"((r)[1]), "=r"((r)[2]), "=r"((r)[3]) : "r"(addr))
#define LDSM_X4_T(r, addr) \
    asm volatile("ldmatrix.sync.aligned.m8n8.x4.trans.shared.b16 {%0,%1,%2,%3}, [%4];" \
        : "=r"((r)[0]), "=r"((r)[1]), "=r"((r)[2]), "=r"((r)[3]) : "r"(addr))
#define MMA_BF16(d, a, b) \
    asm volatile("mma.sync.aligned.m16n8k16.row.col.f32.bf16.bf16.f32 " \
        "{%0,%1,%2,%3}, {%4,%5,%6,%7}, {%8,%9}, {%0,%1,%2,%3};" \
        : "+f"((d)[0]), "+f"((d)[1]), "+f"((d)[2]), "+f"((d)[3]) \
        : "r"((a)[0]), "r"((a)[1]), "r"((a)[2]), "r"((a)[3]), "r"((b)[0]), "r"((b)[1]))

__device__ __forceinline__ void split_bf16(float x, __nv_bfloat16& h, __nv_bfloat16& l) {
    h = __float2bfloat16(x);
    l = __float2bfloat16(x - __bfloat162float(h));
}
__device__ __forceinline__ unsigned pk2(__nv_bfloat16 a, __nv_bfloat16 b) {
    __nv_bfloat162 t = __halves2bfloat162(a, b);
    return *reinterpret_cast<unsigned*>(&t);
}

// ---------------------------------------------------------------------------
// Prep: W[k][c] -> Wt hi/lo [c][k] bf16 (4 matrices, z-indexed)
// ---------------------------------------------------------------------------
__global__ void __launch_bounds__(256) prep_w_kernel(
    const float* __restrict__ Wq, const float* __restrict__ Wk,
    const float* __restrict__ Wv, const float* __restrict__ Wo)
{
    const float* W = (blockIdx.z == 0) ? Wq : (blockIdx.z == 1) ? Wk
                   : (blockIdx.z == 2) ? Wv : Wo;
    __nv_bfloat16* oh = g_wt_hi + (size_t)blockIdx.z * 512 * 512;
    __nv_bfloat16* ol = g_wt_lo + (size_t)blockIdx.z * 512 * 512;
    __shared__ float tl[32][33];
    const int k0 = blockIdx.x * 32, c0 = blockIdx.y * 32;
    const int tx = threadIdx.x, ty = threadIdx.y;
#pragma unroll
    for (int i = 0; i < 4; i++)
        tl[ty + 8*i][tx] = W[(size_t)(k0 + ty + 8*i) * 512 + c0 + tx];
    __syncthreads();
#pragma unroll
    for (int i = 0; i < 4; i++) {
        const int r = ty + 8*i;
        const float v = tl[tx][r];
        __nv_bfloat16 h, l; split_bf16(v, h, l);
        oh[(size_t)(c0 + r) * 512 + k0 + tx] = h;
        ol[(size_t)(c0 + r) * 512 + k0 + tx] = l;
    }
}

// img [b][k][s] -> imgT hi/lo [b][s][k]
__global__ void __launch_bounds__(256) prep_img_kernel(const float* __restrict__ img)
{
    __shared__ float tl[32][33];
    const int s0 = blockIdx.x * 32, k0 = blockIdx.y * 32, b = blockIdx.z;
    const int tx = threadIdx.x, ty = threadIdx.y;
#pragma unroll
    for (int i = 0; i < 4; i++)
        tl[ty + 8*i][tx] = img[((size_t)b*CI + k0 + ty + 8*i) * HW + s0 + tx];
    __syncthreads();
#pragma unroll
    for (int i = 0; i < 4; i++) {
        const int r = ty + 8*i;
        const float v = tl[tx][r];
        __nv_bfloat16 h, l; split_bf16(v, h, l);
        const size_t o = ((size_t)b*HW + s0 + r) * 512 + k0 + tx;
        g_imgT_hi[o] = h;
        g_imgT_lo[o] = l;
    }
}

// audio fp32 -> hi/lo bf16
__global__ void __launch_bounds__(256) prep_aud_kernel(const float* __restrict__ aud)
{
    const int i = blockIdx.x * 256 + threadIdx.x;
    float4 v = ((const float4*)aud)[i];
    __nv_bfloat16 h0,l0,h1,l1,h2,l2,h3,l3;
    split_bf16(v.x,h0,l0); split_bf16(v.y,h1,l1);
    split_bf16(v.z,h2,l2); split_bf16(v.w,h3,l3);
    ((uint2*)g_aud_hi)[i] = make_uint2(pk2(h0,h1), pk2(h2,h3));
    ((uint2*)g_aud_lo)[i] = make_uint2(pk2(l0,l1), pk2(l2,l3));
}

// ---------------------------------------------------------------------------
// mma.sync GEMM (unchanged from R5): 128x128 CTA tile, 8 warps 4m x 2n.
// ---------------------------------------------------------------------------
#define SM_BIAS    0
#define SM_TILES   512
#define ROW_B      80
#define TILE_B     (128*ROW_B)
#define STAGE_B    (4*TILE_B)
#define GEMM_SMEM  (SM_TILES + 2*STAGE_B)

__device__ __forceinline__ void fill_tiles(char* dst, const char* Ah, const char* Al,
                                           const char* Bh, const char* Bl,
                                           int chunk, int t)
{
    const size_t kb = (size_t)chunk * 64;
    const char* srcs[4] = { Ah + kb, Al + kb, Bh + kb, Bl + kb };
#pragma unroll
    for (int w = 0; w < 4; w++) {
        const char* s = srcs[w];
        char* d = dst + w * TILE_B;
#pragma unroll
        for (int it = 0; it < 2; it++) {
            const int idx = t + 256 * it;
            const int row = idx >> 2, q = (idx & 3) * 16;
            *(uint4*)(d + row * ROW_B + q) = *(const uint4*)(s + (size_t)row * 1024 + q);
        }
    }
}

template<int MODE>
__global__ void __launch_bounds__(256) gemm_mma(const float* __restrict__ bias)
{
    extern __shared__ char smem[];
    const uint32_t su = smem_to_u32(smem);
    const int t = threadIdx.x, wid = t >> 5, lane = t & 31;
    const int warp_m = wid >> 1, warp_n = wid & 1;

    constexpr int   Mtot  = (MODE == 0 || MODE == 3) ? 1024 : 256;
    constexpr float SCALE = (MODE == 0) ? 0.125f : 1.0f;
    const __nv_bfloat16* Ah = (MODE == 0) ? g_imgT_hi : (MODE == 3) ? g_attn_hi : g_aud_hi;
    const __nv_bfloat16* Al = (MODE == 0) ? g_imgT_lo : (MODE == 3) ? g_attn_lo : g_aud_lo;
    float* out = (MODE == 0) ? g_q : (MODE == 1) ? g_k : (MODE == 2) ? g_v : g_y;

    const int m0 = blockIdx.x * 128, c0 = blockIdx.y * 128, b = blockIdx.z;

    float* sbias = (float*)(smem + SM_BIAS);
    if (t < 128) sbias[t] = bias[c0 + t];

    const char* Acta_h = (const char*)(Ah + ((size_t)b * Mtot + m0) * 512);
    const char* Acta_l = (const char*)(Al + ((size_t)b * Mtot + m0) * 512);
    const char* Bcta_h = (const char*)(g_wt_hi + (size_t)MODE * 512 * 512 + (size_t)c0 * 512);
    const char* Bcta_l = (const char*)(g_wt_lo + (size_t)MODE * 512 * 512 + (size_t)c0 * 512);

    float acc[2][8][4];
#pragma unroll
    for (int mt = 0; mt < 2; mt++)
#pragma unroll
        for (int nt = 0; nt < 8; nt++)
#pragma unroll
            for (int r = 0; r < 4; r++) acc[mt][nt][r] = 0.f;

    const int a_row  = (lane & 15);
    const int a_koff = (lane >> 4) << 4;
    const int b_row  = (lane & 7) + ((lane >> 4) << 3);
    const int b_koff = ((lane >> 3) & 1) << 4;

    fill_tiles(smem + SM_TILES, Acta_h, Acta_l, Bcta_h, Bcta_l, 0, t);
    __syncthreads();

    for (int c = 0; c < 16; c++) {
        const int st = c & 1;
        if (c + 1 < 16)
            fill_tiles(smem + SM_TILES + (st ^ 1) * STAGE_B,
                       Acta_h, Acta_l, Bcta_h, Bcta_l, c + 1, t);

        const uint32_t sbase = su + SM_TILES + st * STAGE_B;
        const uint32_t aBase = sbase + (warp_m * 32 + a_row) * ROW_B + a_koff;
        const uint32_t bBase = sbase + 2 * TILE_B + (warp_n * 64 + b_row) * ROW_B + b_koff;

#pragma unroll
        for (int ks = 0; ks < 2; ks++) {
            uint32_t afrag[2][2][4];
#pragma unroll
            for (int mt = 0; mt < 2; mt++)
#pragma unroll
                for (int p = 0; p < 2; p++)
                    LDSM_X4(afrag[mt][p], aBase + p * TILE_B + mt * 16 * ROW_B + ks * 32);

            uint32_t bfrag[8][2][2];
#pragma unroll
            for (int n2 = 0; n2 < 4; n2++)
#pragma unroll
                for (int p = 0; p < 2; p++) {
                    uint32_t r[4];
                    LDSM_X4(r, bBase + p * TILE_B + n2 * 16 * ROW_B + ks * 32);
                    bfrag[2*n2][p][0]   = r[0]; bfrag[2*n2][p][1]   = r[1];
                    bfrag[2*n2+1][p][0] = r[2]; bfrag[2*n2+1][p][1] = r[3];
                }

#pragma unroll
            for (int mt = 0; mt < 2; mt++)
#pragma unroll
                for (int nt = 0; nt < 8; nt++) {
                    MMA_BF16(acc[mt][nt], afrag[mt][0], bfrag[nt][0]);
                    MMA_BF16(acc[mt][nt], afrag[mt][0], bfrag[nt][1]);
                    MMA_BF16(acc[mt][nt], afrag[mt][1], bfrag[nt][0]);
                }
        }
        __syncthreads();
    }

    const int row_base = b * Mtot + m0 + warp_m * 32 + (lane >> 2);
    const int cl_base  = warp_n * 64 + (lane & 3) * 2;
#pragma unroll
    for (int mt = 0; mt < 2; mt++) {
#pragma unroll
        for (int nt = 0; nt < 8; nt++) {
            const int cl = cl_base + nt * 8;
            const float b0 = sbias[cl], b1 = sbias[cl + 1];
            float2 v0, v1;
            v0.x = (acc[mt][nt][0] + b0) * SCALE;
            v0.y = (acc[mt][nt][1] + b1) * SCALE;
            v1.x = (acc[mt][nt][2] + b0) * SCALE;
            v1.y = (acc[mt][nt][3] + b1) * SCALE;
            const int r0 = row_base + mt * 16;
            *(float2*)&out[(size_t)r0 * 512 + c0 + cl]       = v0;
            *(float2*)&out[(size_t)(r0 + 8) * 512 + c0 + cl] = v1;
        }
    }
}

// ---------------------------------------------------------------------------
// Attention via mma.sync: one CTA per (b, h, 128-query tile). 256 threads.
// S = QK^T (bf16-split, 3 MMA), smem softmax, O = PV (bf16-split, 3 MMA).
// smem: S fp32 [128][260] | Q hi/lo [128]x144B (reused for P) | K hi/lo
// [64]x144B (reused for V).
// ---------------------------------------------------------------------------
#define AT_ROW   144                       // 64 bf16 (128B) + 16B pad
#define AT_S     0
#define AT_QH    133120                    // 128*260*4
#define AT_QL    (AT_QH + 128*AT_ROW)      // +18432
#define AT_KH    (AT_QL + 128*AT_ROW)
#define AT_KL    (AT_KH + 64*AT_ROW)
#define ATTN_SMEM_BYTES (AT_KL + 64*AT_ROW)   // 188416
#define S_PAD 260

__global__ void __launch_bounds__(256) attn_mma_kernel()
{
    extern __shared__ char smc[];
    float* S = (float*)smc;
    const uint32_t su = smem_to_u32(smc);

    const int s0 = blockIdx.x * 128;
    const int h  = blockIdx.y;
    const int b  = blockIdx.z;
    const int t  = threadIdx.x;
    const int lane = t & 31, wid = t >> 5;
    const int wm = wid >> 1, wn = wid & 1;       // 4m x 2n warps

    const float* qb = g_q + ((size_t)b*HW + s0)*CA + h*HD;
    const float* kb = g_k + (size_t)b*KL*CA + h*HD;
    const float* vb = g_v + (size_t)b*KL*CA + h*HD;

    // ---- split Q into smem hi/lo ----
#pragma unroll
    for (int it = 0; it < 8; it++) {
        const int idx = t + 256*it;
        const int r = idx >> 4, d4 = (idx & 15) * 4;
        float4 v = *(const float4*)&qb[(size_t)r*CA + d4];
        __nv_bfloat16 h0,l0,h1,l1,h2,l2,h3,l3;
        split_bf16(v.x,h0,l0); split_bf16(v.y,h1,l1);
        split_bf16(v.z,h2,l2); split_bf16(v.w,h3,l3);
        char* ph = smc + AT_QH + r*AT_ROW + d4*2;
        char* pl = smc + AT_QL + r*AT_ROW + d4*2;
        *(unsigned*)ph = pk2(h0,h1); *(unsigned*)(ph+4) = pk2(h2,h3);
        *(unsigned*)pl = pk2(l0,l1); *(unsigned*)(pl+4) = pk2(l2,l3);
    }

    // ldmatrix lane addressing
    const int a_row  = lane & 15;
    const int a_koff = (lane >> 4) << 4;
    const int b_row  = (lane & 7) + ((lane >> 4) << 3);
    const int b_koff = ((lane >> 3) & 1) << 4;
    const int vt_krow = (lane & 7) + (((lane >> 3) & 1) << 3);
    const int vt_noff = (lane >> 4) << 3;

    // ---- S = Q K^T over 4 key chunks ----
    for (int kc = 0; kc < 4; kc++) {
        __syncthreads();
#pragma unroll
        for (int it = 0; it < 4; it++) {
            const int idx = t + 256*it;
            const int key = idx >> 4, d4 = (idx & 15) * 4;
            float4 v = *(const float4*)&kb[(size_t)(kc*64 + key)*CA + d4];
            __nv_bfloat16 h0,l0,h1,l1,h2,l2,h3,l3;
            split_bf16(v.x,h0,l0); split_bf16(v.y,h1,l1);
            split_bf16(v.z,h2,l2); split_bf16(v.w,h3,l3);
            char* ph = smc + AT_KH + key*AT_ROW + d4*2;
            char* pl = smc + AT_KL + key*AT_ROW + d4*2;
            *(unsigned*)ph = pk2(h0,h1); *(unsigned*)(ph+4) = pk2(h2,h3);
            *(unsigned*)pl = pk2(l0,l1); *(unsigned*)(pl+4) = pk2(l2,l3);
        }
        __syncthreads();

        float acc[2][4][4];
#pragma unroll
        for (int mt = 0; mt < 2; mt++)
#pragma unroll
            for (int nt = 0; nt < 4; nt++)
#pragma unroll
                for (int r = 0; r < 4; r++) acc[mt][nt][r] = 0.f;

        const uint32_t aB[2] = { su + AT_QH + (wm*32 + a_row)*AT_ROW + a_koff,
                                 su + AT_QL + (wm*32 + a_row)*AT_ROW + a_koff };
        const uint32_t bB[2] = { su + AT_KH + (wn*32 + b_row)*AT_ROW + b_koff,
                                 su + AT_KL + (wn*32 + b_row)*AT_ROW + b_koff };

#pragma unroll
        for (int ks = 0; ks < 4; ks++) {
            uint32_t af[2][2][4];
#pragma unroll
            for (int mt = 0; mt < 2; mt++)
#pragma unroll
                for (int p = 0; p < 2; p++)
                    LDSM_X4(af[mt][p], aB[p] + mt*16*AT_ROW + ks*32);
            uint32_t bf[4][2][2];
#pragma unroll
            for (int n2 = 0; n2 < 2; n2++)
#pragma unroll
                for (int p = 0; p < 2; p++) {
                    uint32_t r[4];
                    LDSM_X4(r, bB[p] + n2*16*AT_ROW + ks*32);
                    bf[2*n2][p][0]   = r[0]; bf[2*n2][p][1]   = r[1];
                    bf[2*n2+1][p][0] = r[2]; bf[2*n2+1][p][1] = r[3];
                }
#pragma unroll
            for (int mt = 0; mt < 2; mt++)
#pragma unroll
                for (int nt = 0; nt < 4; nt++) {
                    MMA_BF16(acc[mt][nt], af[mt][0], bf[nt][0]);
                    MMA_BF16(acc[mt][nt], af[mt][0], bf[nt][1]);
                    MMA_BF16(acc[mt][nt], af[mt][1], bf[nt][0]);
                }
        }

        const int sr = wm*32 + (lane >> 2);
        const int sc = kc*64 + wn*32 + (lane & 3)*2;
#pragma unroll
        for (int mt = 0; mt < 2; mt++)
#pragma unroll
            for (int nt = 0; nt < 4; nt++) {
                *(float2*)&S[(sr + mt*16    )*S_PAD + sc + nt*8] =
                    make_float2(acc[mt][nt][0], acc[mt][nt][1]);
                *(float2*)&S[(sr + mt*16 + 8)*S_PAD + sc + nt*8] =
                    make_float2(acc[mt][nt][2], acc[mt][nt][3]);
            }
    }
    __syncthreads();

    // ---- softmax over 256 keys, one warp per 16 rows ----
    {
        const int wd = t >> 5, lid = t & 31;
        for (int ri = 0; ri < 16; ri++) {
            const int r = wd*16 + ri;
            float vals[8];
            float m = -1e30f;
#pragma unroll
            for (int ii = 0; ii < 8; ii++) {
                vals[ii] = S[r*S_PAD + lid + 32*ii];
                m = fmaxf(m, vals[ii]);
            }
#pragma unroll
            for (int off = 16; off; off >>= 1) m = fmaxf(m, __shfl_xor_sync(0xffffffffu, m, off));
            float sum = 0.f;
#pragma unroll
            for (int ii = 0; ii < 8; ii++) { vals[ii] = __expf(vals[ii] - m); sum += vals[ii]; }
#pragma unroll
            for (int off = 16; off; off >>= 1) sum += __shfl_xor_sync(0xffffffffu, sum, off);
            const float inv = 1.f / sum;
#pragma unroll
            for (int ii = 0; ii < 8; ii++) S[r*S_PAD + lid + 32*ii] = vals[ii] * inv;
        }
    }

    // ---- O = P V over 4 key chunks ----
    float oacc[2][4][4];
#pragma unroll
    for (int mt = 0; mt < 2; mt++)
#pragma unroll
        for (int nt = 0; nt < 4; nt++)
#pragma unroll
            for (int r = 0; r < 4; r++) oacc[mt][nt][r] = 0.f;

    for (int kc = 0; kc < 4; kc++) {
        __syncthreads();
        // split P chunk (from S) into Q-buffer (reused)
#pragma unroll
        for (int it = 0; it < 8; it++) {
            const int idx = t + 256*it;
            const int r = idx >> 4, c4 = (idx & 15) * 4;
            float4 v = *(const float4*)&S[r*S_PAD + kc*64 + c4];
            __nv_bfloat16 h0,l0,h1,l1,h2,l2,h3,l3;
            split_bf16(v.x,h0,l0); split_bf16(v.y,h1,l1);
            split_bf16(v.z,h2,l2); split_bf16(v.w,h3,l3);
            char* ph = smc + AT_QH + r*AT_ROW + c4*2;
            char* pl = smc + AT_QL + r*AT_ROW + c4*2;
            *(unsigned*)ph = pk2(h0,h1); *(unsigned*)(ph+4) = pk2(h2,h3);
            *(unsigned*)pl = pk2(l0,l1); *(unsigned*)(pl+4) = pk2(l2,l3);
        }
        // split V chunk into K-buffer (reused), row-major [key][d]
#pragma unroll
        for (int it = 0; it < 4; it++) {
            const int idx = t + 256*it;
            const int key = idx >> 4, d4 = (idx & 15) * 4;
            float4 v = *(const float4*)&vb[(size_t)(kc*64 + key)*CA + d4];
            __nv_bfloat16 h0,l0,h1,l1,h2,l2,h3,l3;
            split_bf16(v.x,h0,l0); split_bf16(v.y,h1,l1);
            split_bf16(v.z,h2,l2); split_bf16(v.w,h3,l3);
            char* ph = smc + AT_KH + key*AT_ROW + d4*2;
            char* pl = smc + AT_KL + key*AT_ROW + d4*2;
            *(unsigned*)ph = pk2(h0,h1); *(unsigned*)(ph+4) = pk2(h2,h3);
            *(unsigned*)pl = pk2(l0,l1); *(unsigned*)(pl+4) = pk2(l2,l3);
        }
        __syncthreads();

        const uint32_t aB[2] = { su + AT_QH + (wm*32 + a_row)*AT_ROW + a_koff,
                                 su + AT_QL + (wm*32 + a_row)*AT_ROW + a_koff };
        // V^T fragments via ldmatrix.trans on row-major [key][d]
        const uint32_t vB[2] = { su + AT_KH + vt_krow*AT_ROW + (wn*32 + vt_noff)*2,
                                 su + AT_KL + vt_krow*AT_ROW + (wn*32 + vt_noff)*2 };

#pragma unroll
        for (int ks = 0; ks < 4; ks++) {          // key16 steps within chunk
            uint32_t af[2][2][4];
#pragma unroll
            for (int mt = 0; mt < 2; mt++)
#pragma unroll
                for (int p = 0; p < 2; p++)
                    LDSM_X4(af[mt][p], aB[p] + mt*16*AT_ROW + ks*32);
            uint32_t bf[4][2][2];
#pragma unroll
            for (int n2 = 0; n2 < 2; n2++)
#pragma unroll
                for (int p = 0; p < 2; p++) {
                    uint32_t r[4];
                    LDSM_X4_T(r, vB[p] + ks*16*AT_ROW + n2*32);
                    bf[2*n2][p][0]   = r[0]; bf[2*n2][p][1]   = r[1];
                    bf[2*n2+1][p][0] = r[2]; bf[2*n2+1][p][1] = r[3];
                }
#pragma unroll
            for (int mt = 0; mt < 2; mt++)
#pragma unroll
                for (int nt = 0; nt < 4; nt++) {
                    MMA_BF16(oacc[mt][nt], af[mt][0], bf[nt][0]);
                    MMA_BF16(oacc[mt][nt], af[mt][0], bf[nt][1]);
                    MMA_BF16(oacc[mt][nt], af[mt][1], bf[nt][0]);
                }
        }
    }

    // ---- epilogue: split O into g_attn hi/lo ----
    const int orow = wm*32 + (lane >> 2);
    const int ocol = h*HD + wn*32 + (lane & 3)*2;
#pragma unroll
    for (int mt = 0; mt < 2; mt++)
#pragma unroll
        for (int nt = 0; nt < 4; nt++) {
            const size_t r0 = (size_t)b*HW + s0 + orow + mt*16;
            const int c = ocol + nt*8;
            __nv_bfloat16 h0,l0,h1,l1;
            split_bf16(oacc[mt][nt][0], h0, l0);
            split_bf16(oacc[mt][nt][1], h1, l1);
            *(unsigned*)&g_attn_hi[r0*CA + c] = pk2(h0,h1);
            *(unsigned*)&g_attn_lo[r0*CA + c] = pk2(l0,l1);
            split_bf16(oacc[mt][nt][2], h0, l0);
            split_bf16(oacc[mt][nt][3], h1, l1);
            *(unsigned*)&g_attn_hi[(r0+8)*CA + c] = pk2(h0,h1);
            *(unsigned*)&g_attn_lo[(r0+8)*CA + c] = pk2(l0,l1);
        }
}

// ---------------------------------------------------------------------------
// LayerNorm: y = proj + img (residual), normalize over c, transpose to NCHW
// ---------------------------------------------------------------------------
#define LN_PAD 513
#define LN_SMEM_FLOATS (32*LN_PAD + 64)

__global__ void __launch_bounds__(256) ln_kernel(
    const float* __restrict__ img,
    const float* __restrict__ gamma, const float* __restrict__ beta,
    float* __restrict__ out)
{
    extern __shared__ float sm[];
    float* tile = sm;
    float* s_mu  = sm + 32*LN_PAD;
    float* s_inv = s_mu + 32;

    const int s0 = blockIdx.x * 32;
    const int b  = blockIdx.y;
    const int t  = threadIdx.x;
    const float* yb = g_y + ((size_t)b*HW + s0) * CI;

#pragma unroll
    for (int it = 0; it < 64; it++) {
        const int idx = t + 256*it;
        const int si = idx >> 9, c = idx & 511;
        tile[si*LN_PAD + c] = yb[(size_t)si*CI + c];
    }
    __syncthreads();
#pragma unroll
    for (int it = 0; it < 64; it++) {
        const int idx = t + 256*it;
        const int c = idx >> 5, si = idx & 31;
        tile[si*LN_PAD + c] += img[((size_t)b*CI + c)*HW + s0 + si];
    }
    __syncthreads();

    {
        const int wd = t >> 5, lid = t & 31;
        for (int rr = 0; rr < 4; rr++) {
            const int si = wd*4 + rr;
            float sum = 0.f, sq = 0.f;
#pragma unroll
            for (int ii = 0; ii < 16; ii++) {
                float x = tile[si*LN_PAD + lid + 32*ii];
                sum += x; sq = fmaf(x, x, sq);
            }
#pragma unroll
            for (int off = 16; off; off >>= 1) {
                sum += __shfl_xor_sync(0xffffffffu, sum, off);
                sq  += __shfl_xor_sync(0xffffffffu, sq,  off);
            }
            if (lid == 0) {
                const float mu  = sum * (1.f/512.f);
                const float var = sq * (1.f/512.f) - mu*mu;
                s_mu[si] = mu;
                s_inv[si] = rsqrtf(var + 1e-5f);
            }
        }
    }
    __syncthreads();

#pragma unroll
    for (int it = 0; it < 64; it++) {
        const int idx = t + 256*it;
        const int c = idx >> 5, si = idx & 31;
        const float x = tile[si*LN_PAD + c];
        out[((size_t)b*CI + c)*HW + s0 + si] =
            (x - s_mu[si]) * s_inv[si] * gamma[c] + beta[c];
    }
}

// ---------------------------------------------------------------------------
extern "C" void kernel_launch(void* const* d_in, const int* in_sizes, int n_in,
                              void* d_out, int out_size)
{
    (void)in_sizes; (void)n_in; (void)out_size;
    const float* img   = (const float*)d_in[0];
    const float* aud   = (const float*)d_in[1];
    const float* Wq    = (const float*)d_in[2];
    const float* bq    = (const float*)d_in[3];
    const float* Wk    = (const float*)d_in[4];
    const float* bk    = (const float*)d_in[5];
    const float* Wv    = (const float*)d_in[6];
    const float* bv    = (const float*)d_in[7];
    const float* Wo    = (const float*)d_in[8];
    const float* bo    = (const float*)d_in[9];
    const float* gamma = (const float*)d_in[10];
    const float* beta  = (const float*)d_in[11];
    float* out = (float*)d_out;

    cudaFuncSetAttribute(gemm_mma<0>, cudaFuncAttributeMaxDynamicSharedMemorySize, GEMM_SMEM);
    cudaFuncSetAttribute(gemm_mma<1>, cudaFuncAttributeMaxDynamicSharedMemorySize, GEMM_SMEM);
    cudaFuncSetAttribute(gemm_mma<2>, cudaFuncAttributeMaxDynamicSharedMemorySize, GEMM_SMEM);
    cudaFuncSetAttribute(gemm_mma<3>, cudaFuncAttributeMaxDynamicSharedMemorySize, GEMM_SMEM);

    prep_w_kernel<<<dim3(16, 16, 4), dim3(32, 8)>>>(Wq, Wk, Wv, Wo);
    prep_img_kernel<<<dim3(32, 16, B_), dim3(32, 8)>>>(img);
    prep_aud_kernel<<<(B_*KL*CA/4)/256, 256>>>(aud);

    gemm_mma<0><<<dim3(8, 4, B_), 256, GEMM_SMEM>>>(bq);
    gemm_mma<1><<<dim3(2, 4, B_), 256, GEMM_SMEM>>>(bk);
    gemm_mma<2><<<dim3(2, 4, B_), 256, GEMM_SMEM>>>(bv);

    cudaFuncSetAttribute(attn_mma_kernel, cudaFuncAttributeMaxDynamicSharedMemorySize,
                         ATTN_SMEM_BYTES);
    attn_mma_kernel<<<dim3(HW/128, NH, B_), 256, ATTN_SMEM_BYTES>>>();

    gemm_mma<3><<<dim3(8, 4, B_), 256, GEMM_SMEM>>>(bo);

    const size_t ln_smem = (size_t)LN_SMEM_FLOATS * sizeof(float);
    cudaFuncSetAttribute(ln_kernel, cudaFuncAttributeMaxDynamicSharedMemorySize, (int)ln_smem);
    ln_kernel<<<dim3(HW/32, B_), 256, ln_smem>>>(img, gamma, beta, out);
}

// round 8
// speedup vs baseline: 3.7854x; 1.0187x over previous
#include <cuda_runtime.h>
#include <cuda_bf16.h>
#include <cstdint>

#define B_  16
#define CI  512
#define HW  1024
#define CA  512
#define KL  256
#define NH  8
#define HD  64

// ---------------------------------------------------------------------------
// Scratch (__device__ globals; allocation-free)
// ---------------------------------------------------------------------------
__device__ float g_y[B_*HW*CI];
__device__ __nv_bfloat16 g_qh[B_*HW*CA],  g_ql[B_*HW*CA];            // scaled Q hi/lo
__device__ __nv_bfloat16 g_kh[B_*KL*CA],  g_kl2[B_*KL*CA];           // K hi/lo
__device__ __nv_bfloat16 g_vh[B_*KL*CA],  g_vl[B_*KL*CA];            // V hi/lo
__device__ __nv_bfloat16 g_imgT_hi[B_*HW*CI], g_imgT_lo[B_*HW*CI];   // [b][s][k]
__device__ __nv_bfloat16 g_aud_hi[B_*KL*CA],  g_aud_lo[B_*KL*CA];    // [b][t][k]
__device__ __nv_bfloat16 g_attn_hi[B_*HW*CA], g_attn_lo[B_*HW*CA];   // [b][s][k]
__device__ __nv_bfloat16 g_wt_hi[4*512*512],  g_wt_lo[4*512*512];    // [widx][c][k]

// ---------------------------------------------------------------------------
// PTX helpers (baseline PTX only: ldmatrix + mma.sync)
// ---------------------------------------------------------------------------
__device__ __forceinline__ uint32_t smem_to_u32(const void* p) {
    uint32_t a;
    asm("{ .reg .u64 t; cvta.to.shared.u64 t, %1; cvt.u32.u64 %0, t; }" : "=r"(a) : "l"(p));
    return a;
}
#define LDSM_X4(r, addr) \
    asm volatile("ldmatrix.sync.aligned.m8n8.x4.shared.b16 {%0,%1,%2,%3}, [%4];" \
        : "=r"((r)[0]), "=r"((r)[1]), "=r"((r)[2]), "=r"((r)[3]) : "r"(addr))
#define LDSM_X4_T(r, addr) \
    asm volatile("ldmatrix.sync.aligned.m8n8.x4.trans.shared.b16 {%0,%1,%2,%3}, [%4];" \
        : "=r"((r)[0]), "=r"((r)[1]), "=r"((r)[2]), "=r"((r)[3]) : "r"(addr))
#define MMA_BF16(d, a, b) \
    asm volatile("mma.sync.aligned.m16n8k16.row.col.f32.bf16.bf16.f32 " \
        "{%0,%1,%2,%3}, {%4,%5,%6,%7}, {%8,%9}, {%0,%1,%2,%3};" \
        : "+f"((d)[0]), "+f"((d)[1]), "+f"((d)[2]), "+f"((d)[3]) \
        : "r"((a)[0]), "r"((a)[1]), "r"((a)[2]), "r"((a)[3]), "r"((b)[0]), "r"((b)[1]))

__device__ __forceinline__ void split_bf16(float x, __nv_bfloat16& h, __nv_bfloat16& l) {
    h = __float2bfloat16(x);
    l = __float2bfloat16(x - __bfloat162float(h));
}
__device__ __forceinline__ unsigned pk2(__nv_bfloat16 a, __nv_bfloat16 b) {
    __nv_bfloat162 t = __halves2bfloat162(a, b);
    return *reinterpret_cast<unsigned*>(&t);
}

// ---------------------------------------------------------------------------
// Prep kernels
// ---------------------------------------------------------------------------
__global__ void __launch_bounds__(256) prep_w_kernel(
    const float* __restrict__ Wq, const float* __restrict__ Wk,
    const float* __restrict__ Wv, const float* __restrict__ Wo)
{
    const float* W = (blockIdx.z == 0) ? Wq : (blockIdx.z == 1) ? Wk
                   : (blockIdx.z == 2) ? Wv : Wo;
    __nv_bfloat16* oh = g_wt_hi + (size_t)blockIdx.z * 512 * 512;
    __nv_bfloat16* ol = g_wt_lo + (size_t)blockIdx.z * 512 * 512;
    __shared__ float tl[32][33];
    const int k0 = blockIdx.x * 32, c0 = blockIdx.y * 32;
    const int tx = threadIdx.x, ty = threadIdx.y;
#pragma unroll
    for (int i = 0; i < 4; i++)
        tl[ty + 8*i][tx] = W[(size_t)(k0 + ty + 8*i) * 512 + c0 + tx];
    __syncthreads();
#pragma unroll
    for (int i = 0; i < 4; i++) {
        const int r = ty + 8*i;
        const float v = tl[tx][r];
        __nv_bfloat16 h, l; split_bf16(v, h, l);
        oh[(size_t)(c0 + r) * 512 + k0 + tx] = h;
        ol[(size_t)(c0 + r) * 512 + k0 + tx] = l;
    }
}

__global__ void __launch_bounds__(256) prep_img_kernel(const float* __restrict__ img)
{
    __shared__ float tl[32][33];
    const int s0 = blockIdx.x * 32, k0 = blockIdx.y * 32, b = blockIdx.z;
    const int tx = threadIdx.x, ty = threadIdx.y;
#pragma unroll
    for (int i = 0; i < 4; i++)
        tl[ty + 8*i][tx] = img[((size_t)b*CI + k0 + ty + 8*i) * HW + s0 + tx];
    __syncthreads();
#pragma unroll
    for (int i = 0; i < 4; i++) {
        const int r = ty + 8*i;
        const float v = tl[tx][r];
        __nv_bfloat16 h, l; split_bf16(v, h, l);
        const size_t o = ((size_t)b*HW + s0 + r) * 512 + k0 + tx;
        g_imgT_hi[o] = h;
        g_imgT_lo[o] = l;
    }
}

__global__ void __launch_bounds__(256) prep_aud_kernel(const float* __restrict__ aud)
{
    const int i = blockIdx.x * 256 + threadIdx.x;
    float4 v = ((const float4*)aud)[i];
    __nv_bfloat16 h0,l0,h1,l1,h2,l2,h3,l3;
    split_bf16(v.x,h0,l0); split_bf16(v.y,h1,l1);
    split_bf16(v.z,h2,l2); split_bf16(v.w,h3,l3);
    ((uint2*)g_aud_hi)[i] = make_uint2(pk2(h0,h1), pk2(h2,h3));
    ((uint2*)g_aud_lo)[i] = make_uint2(pk2(l0,l1), pk2(l2,l3));
}

// ---------------------------------------------------------------------------
// mma.sync GEMM: 128x128 CTA tile, 8 warps 4m x 2n, BK=32 double-buffered.
// MODE 0: Q -> g_qh/g_ql (scaled bf16 split)
// MODE 1: fused K+V -> g_kh/g_kl2, g_vh/g_vl (blockIdx.y selects matrix+c tile)
// MODE 3: O -> g_y (fp32)
// ---------------------------------------------------------------------------
#define SM_BIAS    0
#define SM_TILES   512
#define ROW_B      80
#define TILE_B     (128*ROW_B)
#define STAGE_B    (4*TILE_B)
#define GEMM_SMEM  (SM_TILES + 2*STAGE_B)

__device__ __forceinline__ void fill_tiles(char* dst, const char* Ah, const char* Al,
                                           const char* Bh, const char* Bl,
                                           int chunk, int t)
{
    const size_t kb = (size_t)chunk * 64;
    const char* srcs[4] = { Ah + kb, Al + kb, Bh + kb, Bl + kb };
#pragma unroll
    for (int w = 0; w < 4; w++) {
        const char* s = srcs[w];
        char* d = dst + w * TILE_B;
#pragma unroll
        for (int it = 0; it < 2; it++) {
            const int idx = t + 256 * it;
            const int row = idx >> 2, q = (idx & 3) * 16;
            *(uint4*)(d + row * ROW_B + q) = *(const uint4*)(s + (size_t)row * 1024 + q);
        }
    }
}

template<int MODE>
__global__ void __launch_bounds__(256) gemm_mma(const float* __restrict__ bias,
                                                const float* __restrict__ bias2)
{
    extern __shared__ char smem[];
    const uint32_t su = smem_to_u32(smem);
    const int t = threadIdx.x, wid = t >> 5, lane = t & 31;
    const int warp_m = wid >> 1, warp_n = wid & 1;

    constexpr int Mtot = (MODE == 1) ? 256 : 1024;
    const int b = blockIdx.z;
    const int m0 = blockIdx.x * 128;
    int c0, widx;
    const float* bsrc;
    if (MODE == 1) { widx = 1 + (blockIdx.y >> 2); c0 = (blockIdx.y & 3) * 128;
                     bsrc = (widx == 1) ? bias : bias2; }
    else           { widx = (MODE == 0) ? 0 : 3;   c0 = blockIdx.y * 128; bsrc = bias; }

    const __nv_bfloat16* Ah = (MODE == 0) ? g_imgT_hi : (MODE == 3) ? g_attn_hi : g_aud_hi;
    const __nv_bfloat16* Al = (MODE == 0) ? g_imgT_lo : (MODE == 3) ? g_attn_lo : g_aud_lo;

    float* sbias = (float*)(smem + SM_BIAS);
    if (t < 128) sbias[t] = bsrc[c0 + t];

    const char* Acta_h = (const char*)(Ah + ((size_t)b * Mtot + m0) * 512);
    const char* Acta_l = (const char*)(Al + ((size_t)b * Mtot + m0) * 512);
    const char* Bcta_h = (const char*)(g_wt_hi + (size_t)widx * 512 * 512 + (size_t)c0 * 512);
    const char* Bcta_l = (const char*)(g_wt_lo + (size_t)widx * 512 * 512 + (size_t)c0 * 512);

    float acc[2][8][4];
#pragma unroll
    for (int mt = 0; mt < 2; mt++)
#pragma unroll
        for (int nt = 0; nt < 8; nt++)
#pragma unroll
            for (int r = 0; r < 4; r++) acc[mt][nt][r] = 0.f;

    const int a_row  = (lane & 15);
    const int a_koff = (lane >> 4) << 4;
    const int b_row  = (lane & 7) + ((lane >> 4) << 3);
    const int b_koff = ((lane >> 3) & 1) << 4;

    fill_tiles(smem + SM_TILES, Acta_h, Acta_l, Bcta_h, Bcta_l, 0, t);
    __syncthreads();

    for (int c = 0; c < 16; c++) {
        const int st = c & 1;
        if (c + 1 < 16)
            fill_tiles(smem + SM_TILES + (st ^ 1) * STAGE_B,
                       Acta_h, Acta_l, Bcta_h, Bcta_l, c + 1, t);

        const uint32_t sbase = su + SM_TILES + st * STAGE_B;
        const uint32_t aBase = sbase + (warp_m * 32 + a_row) * ROW_B + a_koff;
        const uint32_t bBase = sbase + 2 * TILE_B + (warp_n * 64 + b_row) * ROW_B + b_koff;

#pragma unroll
        for (int ks = 0; ks < 2; ks++) {
            uint32_t afrag[2][2][4];
#pragma unroll
            for (int mt = 0; mt < 2; mt++)
#pragma unroll
                for (int p = 0; p < 2; p++)
                    LDSM_X4(afrag[mt][p], aBase + p * TILE_B + mt * 16 * ROW_B + ks * 32);

            uint32_t bfrag[8][2][2];
#pragma unroll
            for (int n2 = 0; n2 < 4; n2++)
#pragma unroll
                for (int p = 0; p < 2; p++) {
                    uint32_t r[4];
                    LDSM_X4(r, bBase + p * TILE_B + n2 * 16 * ROW_B + ks * 32);
                    bfrag[2*n2][p][0]   = r[0]; bfrag[2*n2][p][1]   = r[1];
                    bfrag[2*n2+1][p][0] = r[2]; bfrag[2*n2+1][p][1] = r[3];
                }

#pragma unroll
            for (int mt = 0; mt < 2; mt++)
#pragma unroll
                for (int nt = 0; nt < 8; nt++) {
                    MMA_BF16(acc[mt][nt], afrag[mt][0], bfrag[nt][0]);
                    MMA_BF16(acc[mt][nt], afrag[mt][0], bfrag[nt][1]);
                    MMA_BF16(acc[mt][nt], afrag[mt][1], bfrag[nt][0]);
                }
        }
        __syncthreads();
    }

    const int row_base = b * Mtot + m0 + warp_m * 32 + (lane >> 2);
    const int cl_base  = warp_n * 64 + (lane & 3) * 2;

    if (MODE == 3) {
        float* out = g_y;
#pragma unroll
        for (int mt = 0; mt < 2; mt++)
#pragma unroll
            for (int nt = 0; nt < 8; nt++) {
                const int cl = cl_base + nt * 8;
                const float b0 = sbias[cl], b1 = sbias[cl + 1];
                const int r0 = row_base + mt * 16;
                *(float2*)&out[(size_t)r0 * 512 + c0 + cl] =
                    make_float2(acc[mt][nt][0] + b0, acc[mt][nt][1] + b1);
                *(float2*)&out[(size_t)(r0 + 8) * 512 + c0 + cl] =
                    make_float2(acc[mt][nt][2] + b0, acc[mt][nt][3] + b1);
            }
    } else {
        constexpr float SCALE = (MODE == 0) ? 0.125f : 1.0f;
        __nv_bfloat16* outh = (MODE == 0) ? g_qh : (MODE == 1 ? (__nv_bfloat16*)nullptr : nullptr);
        __nv_bfloat16* outl;
        if (MODE == 0) { outh = g_qh; outl = g_ql; }
        else { if ((blockIdx.y >> 2) == 0) { outh = g_kh; outl = g_kl2; }
               else                        { outh = g_vh; outl = g_vl; } }
#pragma unroll
        for (int mt = 0; mt < 2; mt++)
#pragma unroll
            for (int nt = 0; nt < 8; nt++) {
                const int cl = cl_base + nt * 8;
                const float b0 = sbias[cl], b1 = sbias[cl + 1];
                const int r0 = row_base + mt * 16;
                float x0 = (acc[mt][nt][0] + b0) * SCALE;
                float x1 = (acc[mt][nt][1] + b1) * SCALE;
                float x2 = (acc[mt][nt][2] + b0) * SCALE;
                float x3 = (acc[mt][nt][3] + b1) * SCALE;
                __nv_bfloat16 h0,l0,h1,l1;
                split_bf16(x0,h0,l0); split_bf16(x1,h1,l1);
                *(unsigned*)&outh[(size_t)r0*512 + c0 + cl] = pk2(h0,h1);
                *(unsigned*)&outl[(size_t)r0*512 + c0 + cl] = pk2(l0,l1);
                split_bf16(x2,h0,l0); split_bf16(x3,h1,l1);
                *(unsigned*)&outh[(size_t)(r0+8)*512 + c0 + cl] = pk2(h0,h1);
                *(unsigned*)&outl[(size_t)(r0+8)*512 + c0 + cl] = pk2(l0,l1);
            }
    }
}

// ---------------------------------------------------------------------------
// Attention: inputs pre-split bf16. S fp32 in smem; softmax writes P hi/lo
// IN PLACE over the S buffer (row hi at +0, lo at +512 within the 1040B row).
// ---------------------------------------------------------------------------
#define S_ROWB  1040                        // 260 floats
#define AT_ROW  144
#define AT_QH   (128*S_ROWB)                // 133120
#define AT_QL   (AT_QH + 128*AT_ROW)
#define AT_KH   (AT_QL + 128*AT_ROW)
#define AT_KL   (AT_KH + 64*AT_ROW)
#define ATTN_SMEM_BYTES (AT_KL + 64*AT_ROW) // 188416

__global__ void __launch_bounds__(256) attn_mma_kernel()
{
    extern __shared__ char smc[];
    float* S = (float*)smc;
    const uint32_t su = smem_to_u32(smc);

    const int s0 = blockIdx.x * 128;
    const int h  = blockIdx.y;
    const int b  = blockIdx.z;
    const int t  = threadIdx.x;
    const int lane = t & 31, wid = t >> 5;
    const int wm = wid >> 1, wn = wid & 1;

    const __nv_bfloat16* qhp = g_qh + ((size_t)b*HW + s0)*CA + h*HD;
    const __nv_bfloat16* qlp = g_ql + ((size_t)b*HW + s0)*CA + h*HD;
    const __nv_bfloat16* khp = g_kh + (size_t)b*KL*CA + h*HD;
    const __nv_bfloat16* klp = g_kl2 + (size_t)b*KL*CA + h*HD;
    const __nv_bfloat16* vhp = g_vh + (size_t)b*KL*CA + h*HD;
    const __nv_bfloat16* vlp = g_vl + (size_t)b*KL*CA + h*HD;

    // ---- copy pre-split Q into smem (8 uint4 per row per buffer) ----
#pragma unroll
    for (int it = 0; it < 4; it++) {
        const int idx = t + 256*it;
        const int r = idx >> 3, q = (idx & 7) * 16;    // 16B units
        *(uint4*)(smc + AT_QH + r*AT_ROW + q) = *(const uint4*)((const char*)qhp + (size_t)r*1024 + q);
        *(uint4*)(smc + AT_QL + r*AT_ROW + q) = *(const uint4*)((const char*)qlp + (size_t)r*1024 + q);
    }

    const int a_row  = lane & 15;
    const int a_koff = (lane >> 4) << 4;
    const int b_row  = (lane & 7) + ((lane >> 4) << 3);
    const int b_koff = ((lane >> 3) & 1) << 4;
    const int vt_krow = (lane & 7) + (((lane >> 3) & 1) << 3);
    const int vt_noff = (lane >> 4) << 3;

    // ---- S = Q K^T over 4 key chunks ----
    for (int kc = 0; kc < 4; kc++) {
        __syncthreads();
#pragma unroll
        for (int it = 0; it < 2; it++) {
            const int idx = t + 256*it;
            const int key = idx >> 3, q = (idx & 7) * 16;
            *(uint4*)(smc + AT_KH + key*AT_ROW + q) =
                *(const uint4*)((const char*)khp + (size_t)(kc*64 + key)*1024 + q);
            *(uint4*)(smc + AT_KL + key*AT_ROW + q) =
                *(const uint4*)((const char*)klp + (size_t)(kc*64 + key)*1024 + q);
        }
        __syncthreads();

        float acc[2][4][4];
#pragma unroll
        for (int mt = 0; mt < 2; mt++)
#pragma unroll
            for (int nt = 0; nt < 4; nt++)
#pragma unroll
                for (int r = 0; r < 4; r++) acc[mt][nt][r] = 0.f;

        const uint32_t aB[2] = { su + AT_QH + (wm*32 + a_row)*AT_ROW + a_koff,
                                 su + AT_QL + (wm*32 + a_row)*AT_ROW + a_koff };
        const uint32_t bB[2] = { su + AT_KH + (wn*32 + b_row)*AT_ROW + b_koff,
                                 su + AT_KL + (wn*32 + b_row)*AT_ROW + b_koff };

#pragma unroll
        for (int ks = 0; ks < 4; ks++) {
            uint32_t af[2][2][4];
#pragma unroll
            for (int mt = 0; mt < 2; mt++)
#pragma unroll
                for (int p = 0; p < 2; p++)
                    LDSM_X4(af[mt][p], aB[p] + mt*16*AT_ROW + ks*32);
            uint32_t bf[4][2][2];
#pragma unroll
            for (int n2 = 0; n2 < 2; n2++)
#pragma unroll
                for (int p = 0; p < 2; p++) {
                    uint32_t r[4];
                    LDSM_X4(r, bB[p] + n2*16*AT_ROW + ks*32);
                    bf[2*n2][p][0]   = r[0]; bf[2*n2][p][1]   = r[1];
                    bf[2*n2+1][p][0] = r[2]; bf[2*n2+1][p][1] = r[3];
                }
#pragma unroll
            for (int mt = 0; mt < 2; mt++)
#pragma unroll
                for (int nt = 0; nt < 4; nt++) {
                    MMA_BF16(acc[mt][nt], af[mt][0], bf[nt][0]);
                    MMA_BF16(acc[mt][nt], af[mt][0], bf[nt][1]);
                    MMA_BF16(acc[mt][nt], af[mt][1], bf[nt][0]);
                }
        }

        const int sr = wm*32 + (lane >> 2);
        const int sc = kc*64 + wn*32 + (lane & 3)*2;
#pragma unroll
        for (int mt = 0; mt < 2; mt++)
#pragma unroll
            for (int nt = 0; nt < 4; nt++) {
                *(float2*)(smc + (sr + mt*16    )*S_ROWB + (sc + nt*8)*4) =
                    make_float2(acc[mt][nt][0], acc[mt][nt][1]);
                *(float2*)(smc + (sr + mt*16 + 8)*S_ROWB + (sc + nt*8)*4) =
                    make_float2(acc[mt][nt][2], acc[mt][nt][3]);
            }
    }
    __syncthreads();

    // ---- softmax over 256 keys; write P hi/lo IN PLACE over S rows ----
    {
        const int wd = t >> 5, lid = t & 31;
        for (int ri = 0; ri < 16; ri++) {
            const int r = wd*16 + ri;
            float* Srow = (float*)(smc + r*S_ROWB);
            float vals[8];
            float m = -1e30f;
#pragma unroll
            for (int ii = 0; ii < 8; ii++) {
                vals[ii] = Srow[lid + 32*ii];
                m = fmaxf(m, vals[ii]);
            }
#pragma unroll
            for (int off = 16; off; off >>= 1) m = fmaxf(m, __shfl_xor_sync(0xffffffffu, m, off));
            float sum = 0.f;
#pragma unroll
            for (int ii = 0; ii < 8; ii++) { vals[ii] = __expf(vals[ii] - m); sum += vals[ii]; }
#pragma unroll
            for (int off = 16; off; off >>= 1) sum += __shfl_xor_sync(0xffffffffu, sum, off);
            const float inv = 1.f / sum;
            __nv_bfloat16* Ph = (__nv_bfloat16*)(smc + r*S_ROWB);
            __nv_bfloat16* Pl = (__nv_bfloat16*)(smc + r*S_ROWB + 512);
            __syncwarp();   // all lanes finished reading Srow before overwrite
#pragma unroll
            for (int ii = 0; ii < 8; ii++) {
                __nv_bfloat16 hh, ll;
                split_bf16(vals[ii] * inv, hh, ll);
                Ph[lid + 32*ii] = hh;
                Pl[lid + 32*ii] = ll;
            }
        }
    }

    // ---- O = P V over 4 key chunks ----
    float oacc[2][4][4];
#pragma unroll
    for (int mt = 0; mt < 2; mt++)
#pragma unroll
        for (int nt = 0; nt < 4; nt++)
#pragma unroll
            for (int r = 0; r < 4; r++) oacc[mt][nt][r] = 0.f;

    for (int kc = 0; kc < 4; kc++) {
        __syncthreads();
#pragma unroll
        for (int it = 0; it < 2; it++) {
            const int idx = t + 256*it;
            const int key = idx >> 3, q = (idx & 7) * 16;
            *(uint4*)(smc + AT_KH + key*AT_ROW + q) =
                *(const uint4*)((const char*)vhp + (size_t)(kc*64 + key)*1024 + q);
            *(uint4*)(smc + AT_KL + key*AT_ROW + q) =
                *(const uint4*)((const char*)vlp + (size_t)(kc*64 + key)*1024 + q);
        }
        __syncthreads();

        // P fragments from in-place rows (stride S_ROWB, hi at +0, lo at +512)
        const uint32_t aB[2] = { su + (wm*32 + a_row)*S_ROWB + kc*128 + a_koff,
                                 su + (wm*32 + a_row)*S_ROWB + 512 + kc*128 + a_koff };
        const uint32_t vB[2] = { su + AT_KH + vt_krow*AT_ROW + (wn*32 + vt_noff)*2,
                                 su + AT_KL + vt_krow*AT_ROW + (wn*32 + vt_noff)*2 };

#pragma unroll
        for (int ks = 0; ks < 4; ks++) {
            uint32_t af[2][2][4];
#pragma unroll
            for (int mt = 0; mt < 2; mt++)
#pragma unroll
                for (int p = 0; p < 2; p++)
                    LDSM_X4(af[mt][p], aB[p] + mt*16*S_ROWB + ks*32);
            uint32_t bf[4][2][2];
#pragma unroll
            for (int n2 = 0; n2 < 2; n2++)
#pragma unroll
                for (int p = 0; p < 2; p++) {
                    uint32_t r[4];
                    LDSM_X4_T(r, vB[p] + ks*16*AT_ROW + n2*32);
                    bf[2*n2][p][0]   = r[0]; bf[2*n2][p][1]   = r[1];
                    bf[2*n2+1][p][0] = r[2]; bf[2*n2+1][p][1] = r[3];
                }
#pragma unroll
            for (int mt = 0; mt < 2; mt++)
#pragma unroll
                for (int nt = 0; nt < 4; nt++) {
                    MMA_BF16(oacc[mt][nt], af[mt][0], bf[nt][0]);
                    MMA_BF16(oacc[mt][nt], af[mt][0], bf[nt][1]);
                    MMA_BF16(oacc[mt][nt], af[mt][1], bf[nt][0]);
                }
        }
    }

    // ---- epilogue: split O into g_attn hi/lo ----
    const int orow = wm*32 + (lane >> 2);
    const int ocol = h*HD + wn*32 + (lane & 3)*2;
#pragma unroll
    for (int mt = 0; mt < 2; mt++)
#pragma unroll
        for (int nt = 0; nt < 4; nt++) {
            const size_t r0 = (size_t)b*HW + s0 + orow + mt*16;
            const int c = ocol + nt*8;
            __nv_bfloat16 h0,l0,h1,l1;
            split_bf16(oacc[mt][nt][0], h0, l0);
            split_bf16(oacc[mt][nt][1], h1, l1);
            *(unsigned*)&g_attn_hi[r0*CA + c] = pk2(h0,h1);
            *(unsigned*)&g_attn_lo[r0*CA + c] = pk2(l0,l1);
            split_bf16(oacc[mt][nt][2], h0, l0);
            split_bf16(oacc[mt][nt][3], h1, l1);
            *(unsigned*)&g_attn_hi[(r0+8)*CA + c] = pk2(h0,h1);
            *(unsigned*)&g_attn_lo[(r0+8)*CA + c] = pk2(l0,l1);
        }
}

// ---------------------------------------------------------------------------
// LayerNorm: y = proj + img (residual), normalize over c, transpose to NCHW
// ---------------------------------------------------------------------------
#define LN_PAD 513
#define LN_SMEM_FLOATS (32*LN_PAD + 64)

__global__ void __launch_bounds__(256) ln_kernel(
    const float* __restrict__ img,
    const float* __restrict__ gamma, const float* __restrict__ beta,
    float* __restrict__ out)
{
    extern __shared__ float sm[];
    float* tile = sm;
    float* s_mu  = sm + 32*LN_PAD;
    float* s_inv = s_mu + 32;

    const int s0 = blockIdx.x * 32;
    const int b  = blockIdx.y;
    const int t  = threadIdx.x;
    const float* yb = g_y + ((size_t)b*HW + s0) * CI;

#pragma unroll
    for (int it = 0; it < 64; it++) {
        const int idx = t + 256*it;
        const int si = idx >> 9, c = idx & 511;
        tile[si*LN_PAD + c] = yb[(size_t)si*CI + c];
    }
    __syncthreads();
#pragma unroll
    for (int it = 0; it < 64; it++) {
        const int idx = t + 256*it;
        const int c = idx >> 5, si = idx & 31;
        tile[si*LN_PAD + c] += img[((size_t)b*CI + c)*HW + s0 + si];
    }
    __syncthreads();

    {
        const int wd = t >> 5, lid = t & 31;
        for (int rr = 0; rr < 4; rr++) {
            const int si = wd*4 + rr;
            float sum = 0.f, sq = 0.f;
#pragma unroll
            for (int ii = 0; ii < 16; ii++) {
                float x = tile[si*LN_PAD + lid + 32*ii];
                sum += x; sq = fmaf(x, x, sq);
            }
#pragma unroll
            for (int off = 16; off; off >>= 1) {
                sum += __shfl_xor_sync(0xffffffffu, sum, off);
                sq  += __shfl_xor_sync(0xffffffffu, sq,  off);
            }
            if (lid == 0) {
                const float mu  = sum * (1.f/512.f);
                const float var = sq * (1.f/512.f) - mu*mu;
                s_mu[si] = mu;
                s_inv[si] = rsqrtf(var + 1e-5f);
            }
        }
    }
    __syncthreads();

#pragma unroll
    for (int it = 0; it < 64; it++) {
        const int idx = t + 256*it;
        const int c = idx >> 5, si = idx & 31;
        const float x = tile[si*LN_PAD + c];
        out[((size_t)b*CI + c)*HW + s0 + si] =
            (x - s_mu[si]) * s_inv[si] * gamma[c] + beta[c];
    }
}

// ---------------------------------------------------------------------------
extern "C" void kernel_launch(void* const* d_in, const int* in_sizes, int n_in,
                              void* d_out, int out_size)
{
    (void)in_sizes; (void)n_in; (void)out_size;
    const float* img   = (const float*)d_in[0];
    const float* aud   = (const float*)d_in[1];
    const float* Wq    = (const float*)d_in[2];
    const float* bq    = (const float*)d_in[3];
    const float* Wk    = (const float*)d_in[4];
    const float* bk    = (const float*)d_in[5];
    const float* Wv    = (const float*)d_in[6];
    const float* bv    = (const float*)d_in[7];
    const float* Wo    = (const float*)d_in[8];
    const float* bo    = (const float*)d_in[9];
    const float* gamma = (const float*)d_in[10];
    const float* beta  = (const float*)d_in[11];
    float* out = (float*)d_out;

    cudaFuncSetAttribute(gemm_mma<0>, cudaFuncAttributeMaxDynamicSharedMemorySize, GEMM_SMEM);
    cudaFuncSetAttribute(gemm_mma<1>, cudaFuncAttributeMaxDynamicSharedMemorySize, GEMM_SMEM);
    cudaFuncSetAttribute(gemm_mma<3>, cudaFuncAttributeMaxDynamicSharedMemorySize, GEMM_SMEM);

    prep_w_kernel<<<dim3(16, 16, 4), dim3(32, 8)>>>(Wq, Wk, Wv, Wo);
    prep_img_kernel<<<dim3(32, 16, B_), dim3(32, 8)>>>(img);
    prep_aud_kernel<<<(B_*KL*CA/4)/256, 256>>>(aud);

    gemm_mma<0><<<dim3(8, 4, B_), 256, GEMM_SMEM>>>(bq, nullptr);
    gemm_mma<1><<<dim3(2, 8, B_), 256, GEMM_SMEM>>>(bk, bv);   // fused K+V

    cudaFuncSetAttribute(attn_mma_kernel, cudaFuncAttributeMaxDynamicSharedMemorySize,
                         ATTN_SMEM_BYTES);
    attn_mma_kernel<<<dim3(HW/128, NH, B_), 256, ATTN_SMEM_BYTES>>>();

    gemm_mma<3><<<dim3(8, 4, B_), 256, GEMM_SMEM>>>(bo, nullptr);

    const size_t ln_smem = (size_t)LN_SMEM_FLOATS * sizeof(float);
    cudaFuncSetAttribute(ln_kernel, cudaFuncAttributeMaxDynamicSharedMemorySize, (int)ln_smem);
    ln_kernel<<<dim3(HW/32, B_), 256, ln_smem>>>(img, gamma, beta, out);
}